// round 2
// baseline (speedup 1.0000x reference)
#include <cuda_runtime.h>
#include <math.h>

#define BB 4
#define CC 64
#define HH 64
#define WW 64
#define LL 4096      // H*W
#define DD 576       // C*9
#define PW 66        // padded width/height

// ---------------- persistent device scratch (no allocations allowed) ----------------
__device__ float g_xpadR[BB*CC*PW*PW];   // reflect-padded x     (4.46 MB)
__device__ float g_qnT[BB*DD*LL];        // normalized patches, d-major (37.7 MB)
__device__ float g_relu[BB*CC*HH*WW];    // relu(conv1)          (4.19 MB)
__device__ float g_feature[BB*CC*HH*WW]; // conv2 output         (4.19 MB)
__device__ float g_topv[BB*4*LL];        // top-k ranks 1..4 values
__device__ int   g_topi[BB*4*LL];        // top-k ranks 1..4 indices

__device__ __forceinline__ int refl(int t){ return t < 0 ? -t : (t >= 64 ? 126 - t : t); }

// ---------------- K1: reflect pad ----------------
__global__ void pad_kernel(const float* __restrict__ x){
    int b  = blockIdx.y;
    int pr = blockIdx.x;                 // 0..65
    int sr = refl(pr - 1);
    for (int e = threadIdx.x; e < CC*PW; e += blockDim.x){
        int c = e / PW, pc = e % PW;
        int sc = refl(pc - 1);
        g_xpadR[((b*CC + c)*PW + pr)*PW + pc] = x[((b*CC + c)*HH + sr)*WW + sc];
    }
}

// ---------------- K2: build normalized patch matrix, d-major ----------------
__global__ void qn_kernel(){
    int bx = blockIdx.x;
    int b  = bx >> 6, li = bx & 63;      // one image row of queries
    __shared__ float s2[3*PW];
    __shared__ float rn[64];
    // per-pixel squared channel norms for padded rows li..li+2
    for (int e = threadIdx.x; e < 3*PW; e += blockDim.x){
        int r = e / PW, pc = e % PW;
        const float* p = &g_xpadR[((b*CC)*PW + (li + r))*PW + pc];
        float s = 0.f;
        #pragma unroll 8
        for (int c = 0; c < CC; c++){ float v = p[c*PW*PW]; s += v*v; }
        s2[e] = s;
    }
    __syncthreads();
    if (threadIdx.x < 64){
        int lj = threadIdx.x;
        float s = 0.f;
        #pragma unroll
        for (int kh = 0; kh < 3; kh++)
            #pragma unroll
            for (int kw = 0; kw < 3; kw++) s += s2[kh*PW + lj + kw];
        float nrm = sqrtf(s);
        rn[lj] = 1.0f / fmaxf(nrm, 1e-12f);
    }
    __syncthreads();
    // write qnT[b][d][li*64+lj]
    for (int e = threadIdx.x; e < DD*64; e += blockDim.x){
        int d = e >> 6, lj = e & 63;
        int c = d / 9, kh = (d % 9) / 3, kw = d % 3;
        float v = g_xpadR[((b*CC + c)*PW + li + kh)*PW + lj + kw];
        g_qnT[(size_t)(b*DD + d)*LL + li*64 + lj] = v * rn[lj];
    }
}

// ---------------- K3: 3x3 conv (zero pad), optional relu ----------------
__global__ void conv3x3_kernel(const float* __restrict__ xin,
                               const float* __restrict__ w,
                               const float* __restrict__ bias, int mode){
    // mode 0: in = xin, out = g_relu (relu). mode 1: in = g_relu, out = g_feature.
    const float* in = (mode == 0) ? xin : g_relu;
    float* out      = (mode == 0) ? g_relu : g_feature;
    int rg = blockIdx.x, co = blockIdx.y, b = blockIdx.z;
    __shared__ float tile[18*PW];
    float acc[4] = {0.f, 0.f, 0.f, 0.f};
    for (int ci = 0; ci < CC; ci++){
        __syncthreads();
        for (int e = threadIdx.x; e < 18*PW; e += blockDim.x){
            int r = e / PW, cc = e % PW;
            int gr = rg*16 + r - 1, gc = cc - 1;
            float v = 0.f;
            if ((unsigned)gr < 64u && (unsigned)gc < 64u)
                v = in[((b*CC + ci)*HH + gr)*WW + gc];
            tile[e] = v;
        }
        __syncthreads();
        const float* w9 = &w[(co*CC + ci)*9];
        float w0=w9[0],w1=w9[1],w2=w9[2],w3=w9[3],w4=w9[4],w5=w9[5],w6=w9[6],w7=w9[7],w8=w9[8];
        #pragma unroll
        for (int k = 0; k < 4; k++){
            int px = k*256 + threadIdx.x;
            int r = px >> 6, c = px & 63;
            const float* t0 = &tile[r*PW + c];
            acc[k] += t0[0]*w0 + t0[1]*w1 + t0[2]*w2
                    + t0[PW]*w3 + t0[PW+1]*w4 + t0[PW+2]*w5
                    + t0[2*PW]*w6 + t0[2*PW+1]*w7 + t0[2*PW+2]*w8;
        }
    }
    float bv = bias[co];
    #pragma unroll
    for (int k = 0; k < 4; k++){
        int px = k*256 + threadIdx.x;
        int r = px >> 6, c = px & 63;
        float v = acc[k] + bv;
        if (mode == 0) v = fmaxf(v, 0.f);
        out[((b*CC + co)*HH + rg*16 + r)*WW + c] = v;
    }
}

// ---------------- K4: similarity GEMM + streaming top-5 ----------------
// 64 queries x 64 keys per tile, 256 threads, 4x4 register tile, d chunked by 64.
__global__ void simtopk_kernel(){
    extern __shared__ float sm[];
    float* Qs = sm;               // [64][64]  d-major
    float* Ks = sm + 64*64;       // [64][64]
    float* Sc = sm + 2*64*64;     // [64][65]  score staging (padded)
    int b  = blockIdx.x >> 6;
    int q0 = (blockIdx.x & 63) << 6;
    int t  = threadIdx.x;
    int ty = t >> 4, tx = t & 15;
    float tv[5]; int tix[5];
    #pragma unroll
    for (int i = 0; i < 5; i++){ tv[i] = -1e30f; tix[i] = 0; }
    const float* qbase = &g_qnT[(size_t)b*DD*LL];

    for (int kt = 0; kt < 64; kt++){
        int k0 = kt << 6;
        float acc[4][4];
        #pragma unroll
        for (int i = 0; i < 4; i++)
            #pragma unroll
            for (int j = 0; j < 4; j++) acc[i][j] = 0.f;

        for (int ch = 0; ch < 9; ch++){
            __syncthreads();
            #pragma unroll
            for (int e = 0; e < 16; e++){
                int idx = e*256 + t;              // 0..4095
                int dl = idx >> 6, qq = idx & 63;
                const float* row = qbase + (size_t)(ch*64 + dl)*LL;
                Qs[idx] = row[q0 + qq];
                Ks[idx] = row[k0 + qq];
            }
            __syncthreads();
            #pragma unroll 4
            for (int d = 0; d < 64; d++){
                float4 qf = *(const float4*)&Qs[d*64 + ty*4];
                float4 kf = *(const float4*)&Ks[d*64 + tx*4];
                acc[0][0] += qf.x*kf.x; acc[0][1] += qf.x*kf.y; acc[0][2] += qf.x*kf.z; acc[0][3] += qf.x*kf.w;
                acc[1][0] += qf.y*kf.x; acc[1][1] += qf.y*kf.y; acc[1][2] += qf.y*kf.z; acc[1][3] += qf.y*kf.w;
                acc[2][0] += qf.z*kf.x; acc[2][1] += qf.z*kf.y; acc[2][2] += qf.z*kf.z; acc[2][3] += qf.z*kf.w;
                acc[3][0] += qf.w*kf.x; acc[3][1] += qf.w*kf.y; acc[3][2] += qf.w*kf.z; acc[3][3] += qf.w*kf.w;
            }
        }
        __syncthreads();
        #pragma unroll
        for (int i = 0; i < 4; i++)
            #pragma unroll
            for (int j = 0; j < 4; j++)
                Sc[(ty*4 + i)*65 + tx*4 + j] = acc[i][j];
        __syncthreads();
        if (t < 64){
            const float* row = &Sc[t*65];
            for (int j = 0; j < 64; j++){
                float s = row[j];
                if (s > tv[4]){
                    float v0 = s; int i0 = k0 + j;
                    #pragma unroll
                    for (int p = 0; p < 5; p++){
                        if (v0 > tv[p]){
                            float tpv = tv[p]; int tpi = tix[p];
                            tv[p] = v0; tix[p] = i0;
                            v0 = tpv; i0 = tpi;
                        }
                    }
                }
            }
        }
        // next iteration's first __syncthreads() orders scan vs. reloads
    }
    if (t < 64){
        int l = q0 + t;
        #pragma unroll
        for (int r = 1; r < 5; r++){
            g_topv[(b*4 + (r-1))*LL + l] = tv[r];
            g_topi[(b*4 + (r-1))*LL + l] = tix[r];
        }
    }
}

// ---------------- K5: gather+fold texture, 1x1 convs, final output ----------------
__global__ void final_kernel(const float* __restrict__ x,
                             const float* __restrict__ wt1, const float* __restrict__ bt1,
                             const float* __restrict__ wt2, const float* __restrict__ bt2,
                             float* __restrict__ out){
    extern __shared__ float sm[];
    float* Tc   = sm;                    // [256][64]  (aliased as fx[128][64] later)
    float* tex  = sm + 256*64;           // [64][64]
    float* msc  = tex + 64*64;           // [4][64]
    int*   midx = (int*)(msc + 4*64);    // [4][3][64]
    int b = blockIdx.x >> 6, i = blockIdx.x & 63;
    int t = threadIdx.x;

    for (int e = t; e < 4*3*64; e += 256){
        int br = e / 192, rr = (e / 64) % 3, j = e & 63;
        int li = i - 1 + rr;
        int v = 0;
        if ((unsigned)li < 64u) v = g_topi[(b*4 + br)*LL + li*64 + j];
        midx[e] = v;
    }
    { int br = t >> 6, j = t & 63; msc[t] = g_topv[(b*4 + br)*LL + i*64 + j]; }
    __syncthreads();

    // Tcat: 4 branches x 64 channels, per output pixel j of row i
    const float* xp = &g_xpadR[(size_t)b*CC*PW*PW];
    for (int e = t; e < 256*64; e += 256){
        int ci = e >> 6, j = e & 63;
        int br = ci >> 6, c = ci & 63;
        const float* xpc = xp + c*PW*PW;
        float sum = 0.f;
        #pragma unroll
        for (int kh = 0; kh < 3; kh++){
            int li = i + 1 - kh;
            if ((unsigned)li >= 64u) continue;
            int slot = 2 - kh;
            #pragma unroll
            for (int kw = 0; kw < 3; kw++){
                int lj = j + 1 - kw;
                if ((unsigned)lj >= 64u) continue;
                int m  = midx[br*192 + slot*64 + lj];
                int mi = m >> 6, mj = m & 63;
                sum += xpc[(mi + kh)*PW + mj + kw];
            }
        }
        Tc[e] = sum * msc[br*64 + j] * (1.0f/9.0f);
    }
    __syncthreads();

    // texture = wt1 @ Tcat + bt1
    for (int o = t; o < 4096; o += 256){
        int co = o >> 6, j = o & 63;
        float s = bt1[co];
        const float* wr = &wt1[co*256];
        #pragma unroll 8
        for (int ci = 0; ci < 256; ci++) s += wr[ci] * Tc[ci*64 + j];
        tex[o] = s;
    }
    __syncthreads();

    // load feature & x rows into Tc region (now free)
    float* fx = Tc;
    for (int e = t; e < 64*64; e += 256){
        int c0 = e >> 6, j = e & 63;
        fx[e]         = g_feature[((b*CC + c0)*HH + i)*WW + j];
        fx[64*64 + e] = x[((b*CC + c0)*HH + i)*WW + j];
    }
    __syncthreads();

    // y = wt2 @ [feature; x; texture] + bt2
    for (int o = t; o < 4096; o += 256){
        int co = o >> 6, j = o & 63;
        float s = bt2[co];
        const float* wr = &wt2[co*192];
        #pragma unroll 8
        for (int ci = 0; ci < 64; ci++) s += wr[ci]       * fx[ci*64 + j];
        #pragma unroll 8
        for (int ci = 0; ci < 64; ci++) s += wr[64 + ci]  * fx[(64 + ci)*64 + j];
        #pragma unroll 8
        for (int ci = 0; ci < 64; ci++) s += wr[128 + ci] * tex[ci*64 + j];
        out[((b*CC + co)*HH + i)*WW + j] = s;
    }
}

// ---------------- launch ----------------
extern "C" void kernel_launch(void* const* d_in, const int* in_sizes, int n_in,
                              void* d_out, int out_size){
    const float* x   = (const float*)d_in[0];
    const float* w1  = (const float*)d_in[1];
    const float* b1  = (const float*)d_in[2];
    const float* w2  = (const float*)d_in[3];
    const float* b2  = (const float*)d_in[4];
    const float* wt1 = (const float*)d_in[5];
    const float* bt1 = (const float*)d_in[6];
    const float* wt2 = (const float*)d_in[7];
    const float* bt2 = (const float*)d_in[8];
    float* out = (float*)d_out;

    const int SIM_SMEM = (2*64*64 + 64*65) * 4;                 // 49408 B
    const int FIN_SMEM = (256*64 + 64*64 + 4*64) * 4 + 4*3*64*4; // 86016 B
    cudaFuncSetAttribute(simtopk_kernel, cudaFuncAttributeMaxDynamicSharedMemorySize, SIM_SMEM);
    cudaFuncSetAttribute(final_kernel,   cudaFuncAttributeMaxDynamicSharedMemorySize, FIN_SMEM);

    pad_kernel<<<dim3(66, 4), 256>>>(x);
    qn_kernel<<<256, 256>>>();
    conv3x3_kernel<<<dim3(4, 64, 4), 256>>>(x, w1, b1, 0);   // relu(conv1) -> g_relu
    conv3x3_kernel<<<dim3(4, 64, 4), 256>>>(x, w2, b2, 1);   // conv2 -> g_feature
    simtopk_kernel<<<256, 256, SIM_SMEM>>>();
    final_kernel<<<256, 256, FIN_SMEM>>>(x, wt1, bt1, wt2, bt2, out);
}

// round 3
// speedup vs baseline: 2.9648x; 2.9648x over previous
#include <cuda_runtime.h>
#include <math.h>

#define BB 4
#define CC 64
#define HH 64
#define WW 64
#define LL 4096      // H*W
#define PW 66        // padded width/height
#define LP 4356      // 66*66 padded pixels

// ---------------- persistent device scratch ----------------
__device__ __align__(16) float g_xpadR[BB*CC*LP];            // reflect-padded x (4.46 MB)
__device__ __align__(16) float g_G[(size_t)BB*LP*LP];        // pixel gram, 303.6 MB
__device__ float g_rn[BB*LL];                                // reciprocal patch norms
__device__ float g_relu[BB*CC*HH*WW];
__device__ float g_feature[BB*CC*HH*WW];
__device__ float g_topv[BB*4*LL];
__device__ int   g_topi[BB*4*LL];

__device__ __forceinline__ int refl(int t){ return t < 0 ? -t : (t >= 64 ? 126 - t : t); }

// ---------------- K1: reflect pad ----------------
__global__ void pad_kernel(const float* __restrict__ x){
    int b  = blockIdx.y;
    int pr = blockIdx.x;                 // 0..65
    int sr = refl(pr - 1);
    for (int e = threadIdx.x; e < CC*PW; e += blockDim.x){
        int c = e / PW, pc = e % PW;
        int sc = refl(pc - 1);
        g_xpadR[(b*CC + c)*LP + pr*PW + pc] = x[((b*CC + c)*HH + sr)*WW + sc];
    }
}

// ---------------- K2: 3x3 conv (zero pad), optional relu ----------------
__global__ void conv3x3_kernel(const float* __restrict__ xin,
                               const float* __restrict__ w,
                               const float* __restrict__ bias, int mode){
    const float* in = (mode == 0) ? xin : g_relu;
    float* out      = (mode == 0) ? g_relu : g_feature;
    int rg = blockIdx.x, co = blockIdx.y, b = blockIdx.z;
    __shared__ float tile[18*PW];
    float acc[4] = {0.f, 0.f, 0.f, 0.f};
    for (int ci = 0; ci < CC; ci++){
        __syncthreads();
        for (int e = threadIdx.x; e < 18*PW; e += blockDim.x){
            int r = e / PW, cc = e % PW;
            int gr = rg*16 + r - 1, gc = cc - 1;
            float v = 0.f;
            if ((unsigned)gr < 64u && (unsigned)gc < 64u)
                v = in[((b*CC + ci)*HH + gr)*WW + gc];
            tile[e] = v;
        }
        __syncthreads();
        const float* w9 = &w[(co*CC + ci)*9];
        float w0=w9[0],w1=w9[1],w2=w9[2],w3=w9[3],w4=w9[4],w5=w9[5],w6=w9[6],w7=w9[7],w8=w9[8];
        #pragma unroll
        for (int k = 0; k < 4; k++){
            int px = k*256 + threadIdx.x;
            int r = px >> 6, c = px & 63;
            const float* t0 = &tile[r*PW + c];
            acc[k] += t0[0]*w0 + t0[1]*w1 + t0[2]*w2
                    + t0[PW]*w3 + t0[PW+1]*w4 + t0[PW+2]*w5
                    + t0[2*PW]*w6 + t0[2*PW+1]*w7 + t0[2*PW+2]*w8;
        }
    }
    float bv = bias[co];
    #pragma unroll
    for (int k = 0; k < 4; k++){
        int px = k*256 + threadIdx.x;
        int r = px >> 6, c = px & 63;
        float v = acc[k] + bv;
        if (mode == 0) v = fmaxf(v, 0.f);
        out[((b*CC + co)*HH + rg*16 + r)*WW + c] = v;
    }
}

// ---------------- K3: pixel gram GEMM  G = Xpad^T Xpad  (K = 64 channels) ----------------
// 128x128 output tile, 256 threads, 8x8 register tile (split 4+4 for coalescing).
__global__ __launch_bounds__(256, 2) void gram_gemm(){
    extern __shared__ float sg[];
    float* Qs = sg;            // [64][128]
    float* Ks = sg + 64*128;   // [64][128]
    int pt = blockIdx.x, qt = blockIdx.y, b = blockIdx.z;
    int p0 = pt*128, q0 = qt*128;
    int t = threadIdx.x, ty = t >> 4, tx = t & 15;
    const float* xp = &g_xpadR[(size_t)b*CC*LP];

    for (int e = t; e < 64*128; e += 256){
        int d = e >> 7, col = e & 127;
        int p = p0 + col, q = q0 + col;
        Qs[e] = (p < LP) ? xp[(size_t)d*LP + p] : 0.f;
        Ks[e] = (q < LP) ? xp[(size_t)d*LP + q] : 0.f;
    }
    __syncthreads();

    float acc[8][8];
    #pragma unroll
    for (int i = 0; i < 8; i++)
        #pragma unroll
        for (int j = 0; j < 8; j++) acc[i][j] = 0.f;

    #pragma unroll 4
    for (int d = 0; d < 64; d++){
        float4 a0 = *(const float4*)&Qs[d*128 + ty*4];
        float4 a1 = *(const float4*)&Qs[d*128 + 64 + ty*4];
        float4 b0 = *(const float4*)&Ks[d*128 + tx*4];
        float4 b1 = *(const float4*)&Ks[d*128 + 64 + tx*4];
        float ar[8] = {a0.x,a0.y,a0.z,a0.w,a1.x,a1.y,a1.z,a1.w};
        float br[8] = {b0.x,b0.y,b0.z,b0.w,b1.x,b1.y,b1.z,b1.w};
        #pragma unroll
        for (int i = 0; i < 8; i++)
            #pragma unroll
            for (int j = 0; j < 8; j++) acc[i][j] += ar[i]*br[j];
    }

    float* Gb = &g_G[(size_t)b*LP*LP];
    #pragma unroll
    for (int i = 0; i < 8; i++){
        int p = p0 + ((i < 4) ? (ty*4 + i) : (64 + ty*4 + i - 4));
        if (p >= LP) continue;
        #pragma unroll
        for (int half = 0; half < 2; half++){
            int q = q0 + half*64 + tx*4;
            if (q + 4 <= LP){
                float4 v = make_float4(acc[i][half*4], acc[i][half*4+1],
                                       acc[i][half*4+2], acc[i][half*4+3]);
                *(float4*)&Gb[(size_t)p*LP + q] = v;
            } else {
                for (int j = 0; j < 4; j++)
                    if (q + j < LP) Gb[(size_t)p*LP + q + j] = acc[i][half*4 + j];
            }
        }
    }
}

// ---------------- K4: reciprocal patch norms from diag(G) ----------------
__global__ void rn_kernel(){
    int b = blockIdx.y, li = blockIdx.x, lj = threadIdx.x;   // 64 threads
    const float* Gb = &g_G[(size_t)b*LP*LP];
    float s = 0.f;
    #pragma unroll
    for (int kh = 0; kh < 3; kh++)
        #pragma unroll
        for (int kw = 0; kw < 3; kw++){
            int p = (li + kh)*PW + lj + kw;
            s += Gb[(size_t)p*LP + p];
        }
    g_rn[b*LL + li*64 + lj] = 1.0f / fmaxf(sqrtf(s), 1e-12f);
}

// ---------------- K5: S = 9-shift sums of G, scaled; streaming top-5 ----------------
// One block per (batch, query image-row). Loops 64 key tiles. 256 threads.
__global__ __launch_bounds__(256, 3) void stopk_kernel(){
    extern __shared__ float sm[];
    float* Bs  = sm;                 // [3][66][68] = 13464 floats
    float* rnq = sm + 13464;         // [64]
    float* rnk = rnq + 64;           // [64]
    float* Sc  = sm;                 // alias (64*65 < 13464), used after Bs consumed

    int b  = blockIdx.x >> 6;
    int li = blockIdx.x & 63;
    int t  = threadIdx.x, ty = t >> 4, tx = t & 15;
    int tr = t >> 5, tc2 = t & 31;

    if (t < 64) rnq[t] = g_rn[b*LL + li*64 + t];

    float tv[5]; int tix[5];
    #pragma unroll
    for (int i = 0; i < 5; i++){ tv[i] = -1e30f; tix[i] = 0; }

    const float* growbase = &g_G[(size_t)b*LP*LP] + (size_t)(li*PW)*LP;

    for (int mi = 0; mi < 64; mi++){
        __syncthreads();   // previous scan done before Bs overwrite
        if (t < 64) rnk[t] = g_rn[b*LL + mi*64 + t];
        // load 3 x [66][66] G blocks; row index in G = li*66 + row (row = kh*66 + r)
        #pragma unroll
        for (int pass = 0; pass < 25; pass++){
            int row = pass*8 + tr;
            if (row < 198){
                int kh = (row >= 132) ? 2 : ((row >= 66) ? 1 : 0);
                const float2 v = *(const float2*)(growbase + (size_t)row*LP + (mi + kh)*PW + tc2*2);
                *(float2*)&Bs[row*68 + tc2*2] = v;
            }
        }
        if (t < 198){
            int row = t;
            int kh = (row >= 132) ? 2 : ((row >= 66) ? 1 : 0);
            const float2 v = *(const float2*)(growbase + (size_t)row*LP + (mi + kh)*PW + 64);
            *(float2*)&Bs[row*68 + 64] = v;
        }
        __syncthreads();

        // 4x4 S tile per thread: S[i][j] = sum_kh sum_kw Bs[kh][lj0+i+kw][mj0+j+kw]
        int lj0 = ty*4, mj0 = tx*4;
        float S[4][4];
        #pragma unroll
        for (int i = 0; i < 4; i++)
            #pragma unroll
            for (int j = 0; j < 4; j++) S[i][j] = 0.f;

        #pragma unroll
        for (int kh = 0; kh < 3; kh++){
            float w[6][6];
            #pragma unroll
            for (int r = 0; r < 6; r++){
                float4 u = *(const float4*)&Bs[(kh*66 + lj0 + r)*68 + mj0];
                float2 v = *(const float2*)&Bs[(kh*66 + lj0 + r)*68 + mj0 + 4];
                w[r][0]=u.x; w[r][1]=u.y; w[r][2]=u.z; w[r][3]=u.w; w[r][4]=v.x; w[r][5]=v.y;
            }
            #pragma unroll
            for (int kw = 0; kw < 3; kw++)
                #pragma unroll
                for (int i = 0; i < 4; i++)
                    #pragma unroll
                    for (int j = 0; j < 4; j++)
                        S[i][j] += w[i+kw][j+kw];
        }
        __syncthreads();   // all Bs reads done; safe to alias as Sc

        #pragma unroll
        for (int i = 0; i < 4; i++){
            float rq = rnq[lj0 + i];
            #pragma unroll
            for (int j = 0; j < 4; j++)
                Sc[(lj0 + i)*65 + mj0 + j] = S[i][j] * rq * rnk[mj0 + j];
        }
        __syncthreads();

        if (t < 64){
            const float* rowp = &Sc[t*65];
            int k0 = mi << 6;
            for (int j = 0; j < 64; j++){
                float s = rowp[j];
                if (s > tv[4]){
                    float v0 = s; int i0 = k0 + j;
                    #pragma unroll
                    for (int p = 0; p < 5; p++){
                        if (v0 > tv[p]){
                            float tpv = tv[p]; int tpi = tix[p];
                            tv[p] = v0; tix[p] = i0;
                            v0 = tpv; i0 = tpi;
                        }
                    }
                }
            }
        }
    }
    if (t < 64){
        int l = li*64 + t;
        #pragma unroll
        for (int r = 1; r < 5; r++){
            g_topv[(b*4 + (r-1))*LL + l] = tv[r];
            g_topi[(b*4 + (r-1))*LL + l] = tix[r];
        }
    }
}

// ---------------- K6: gather+fold texture, 1x1 convs, final output ----------------
__global__ void final_kernel(const float* __restrict__ x,
                             const float* __restrict__ wt1, const float* __restrict__ bt1,
                             const float* __restrict__ wt2, const float* __restrict__ bt2,
                             float* __restrict__ out){
    extern __shared__ float sm[];
    float* Tc   = sm;                    // [256][64]
    float* tex  = sm + 256*64;           // [64][64]
    float* msc  = tex + 64*64;           // [4][64]
    int*   midx = (int*)(msc + 4*64);    // [4][3][64]
    int b = blockIdx.x >> 6, i = blockIdx.x & 63;
    int t = threadIdx.x;

    for (int e = t; e < 4*3*64; e += 256){
        int br = e / 192, rr = (e / 64) % 3, j = e & 63;
        int li = i - 1 + rr;
        int v = 0;
        if ((unsigned)li < 64u) v = g_topi[(b*4 + br)*LL + li*64 + j];
        midx[e] = v;
    }
    { int br = t >> 6, j = t & 63; msc[t] = g_topv[(b*4 + br)*LL + i*64 + j]; }
    __syncthreads();

    const float* xp = &g_xpadR[(size_t)b*CC*LP];
    for (int e = t; e < 256*64; e += 256){
        int ci = e >> 6, j = e & 63;
        int br = ci >> 6, c = ci & 63;
        const float* xpc = xp + c*LP;
        float sum = 0.f;
        #pragma unroll
        for (int kh = 0; kh < 3; kh++){
            int li = i + 1 - kh;
            if ((unsigned)li >= 64u) continue;
            int slot = 2 - kh;
            #pragma unroll
            for (int kw = 0; kw < 3; kw++){
                int lj = j + 1 - kw;
                if ((unsigned)lj >= 64u) continue;
                int m  = midx[br*192 + slot*64 + lj];
                int mi = m >> 6, mj = m & 63;
                sum += xpc[(mi + kh)*PW + mj + kw];
            }
        }
        Tc[e] = sum * msc[br*64 + j] * (1.0f/9.0f);
    }
    __syncthreads();

    for (int o = t; o < 4096; o += 256){
        int co = o >> 6, j = o & 63;
        float s = bt1[co];
        const float* wr = &wt1[co*256];
        #pragma unroll 8
        for (int ci = 0; ci < 256; ci++) s += wr[ci] * Tc[ci*64 + j];
        tex[o] = s;
    }
    __syncthreads();

    float* fx = Tc;
    for (int e = t; e < 64*64; e += 256){
        int c0 = e >> 6, j = e & 63;
        fx[e]         = g_feature[((b*CC + c0)*HH + i)*WW + j];
        fx[64*64 + e] = x[((b*CC + c0)*HH + i)*WW + j];
    }
    __syncthreads();

    for (int o = t; o < 4096; o += 256){
        int co = o >> 6, j = o & 63;
        float s = bt2[co];
        const float* wr = &wt2[co*192];
        #pragma unroll 8
        for (int ci = 0; ci < 64; ci++) s += wr[ci]       * fx[ci*64 + j];
        #pragma unroll 8
        for (int ci = 0; ci < 64; ci++) s += wr[64 + ci]  * fx[(64 + ci)*64 + j];
        #pragma unroll 8
        for (int ci = 0; ci < 64; ci++) s += wr[128 + ci] * tex[ci*64 + j];
        out[((b*CC + co)*HH + i)*WW + j] = s;
    }
}

// ---------------- launch ----------------
extern "C" void kernel_launch(void* const* d_in, const int* in_sizes, int n_in,
                              void* d_out, int out_size){
    const float* x   = (const float*)d_in[0];
    const float* w1  = (const float*)d_in[1];
    const float* b1  = (const float*)d_in[2];
    const float* w2  = (const float*)d_in[3];
    const float* b2  = (const float*)d_in[4];
    const float* wt1 = (const float*)d_in[5];
    const float* bt1 = (const float*)d_in[6];
    const float* wt2 = (const float*)d_in[7];
    const float* bt2 = (const float*)d_in[8];
    float* out = (float*)d_out;

    const int GEMM_SMEM = 2*64*128*4;                            // 65536 B
    const int STK_SMEM  = (13464 + 128)*4;                       // 54368 B
    const int FIN_SMEM  = (256*64 + 64*64 + 4*64)*4 + 4*3*64*4;  // 86016 B
    cudaFuncSetAttribute(gram_gemm,    cudaFuncAttributeMaxDynamicSharedMemorySize, GEMM_SMEM);
    cudaFuncSetAttribute(stopk_kernel, cudaFuncAttributeMaxDynamicSharedMemorySize, STK_SMEM);
    cudaFuncSetAttribute(final_kernel, cudaFuncAttributeMaxDynamicSharedMemorySize, FIN_SMEM);

    pad_kernel<<<dim3(66, 4), 256>>>(x);
    conv3x3_kernel<<<dim3(4, 64, 4), 256>>>(x, w1, b1, 0);
    conv3x3_kernel<<<dim3(4, 64, 4), 256>>>(x, w2, b2, 1);
    gram_gemm<<<dim3(35, 35, 4), 256, GEMM_SMEM>>>();
    rn_kernel<<<dim3(64, 4), 64>>>();
    stopk_kernel<<<256, 256, STK_SMEM>>>();
    final_kernel<<<256, 256, FIN_SMEM>>>(x, wt1, bt1, wt2, bt2, out);
}

// round 4
// speedup vs baseline: 4.9664x; 1.6751x over previous
#include <cuda_runtime.h>
#include <math.h>

#define BB 4
#define CC 64
#define HH 64
#define WW 64
#define LL 4096      // H*W
#define PW 66        // padded width/height
#define LP 4356      // 66*66 padded pixels

// ---------------- persistent device scratch ----------------
__device__ __align__(16) float g_xpadR[BB*CC*LP];     // reflect-padded x
__device__ __align__(16) float g_xpadZ[BB*CC*LP];     // zero-padded x (borders stay 0 from zero-init)
__device__ __align__(16) float g_reluZ[BB*CC*LP];     // zero-padded relu(conv1) (borders stay 0)
__device__ __align__(16) float g_G[(size_t)BB*LP*LP]; // pixel gram, 303.6 MB
__device__ float g_rn[BB*LL];                         // reciprocal patch norms
__device__ float g_feature[BB*CC*HH*WW];
__device__ float g_topv[BB*4*LL];
__device__ int   g_topi[BB*4*LL];

__device__ __forceinline__ int refl(int t){ return t < 0 ? -t : (t >= 64 ? 126 - t : t); }

// ---------------- K1: build reflect- and zero-padded inputs ----------------
__global__ void pad_kernel(const float* __restrict__ x){
    int b  = blockIdx.y;
    int pr = blockIdx.x;                 // 0..65
    int sr = refl(pr - 1);
    bool rin = (pr >= 1 && pr <= 64);
    for (int e = threadIdx.x; e < CC*PW; e += blockDim.x){
        int c = e / PW, pc = e % PW;
        int sc = refl(pc - 1);
        float v = x[((b*CC + c)*HH + sr)*WW + sc];
        g_xpadR[(b*CC + c)*LP + pr*PW + pc] = v;
        if (rin && pc >= 1 && pc <= 64)
            g_xpadZ[(b*CC + c)*LP + pr*PW + pc] = v;   // interior: reflect == direct
    }
}

// ---------------- K2: 3x3 conv (zero pad) from padded buffers ----------------
// Block = (output row, batch). 256 threads: thread = 4 co x 4 pixels. Weights
// staged in smem in 16-ci chunks; input rows li..li+2 for all 64 ci in smem.
__global__ __launch_bounds__(256, 2) void convg_kernel(const float* __restrict__ w,
                                                       const float* __restrict__ bias,
                                                       int mode){
    extern __shared__ float cs[];
    float* s   = cs;            // [64][3][68] = 13056 floats
    float* wsm = cs + 13056;    // [64co][16ci][9] = 9216 floats
    int li = blockIdx.x, b = blockIdx.y;
    const float* in = (mode == 0) ? g_xpadZ : g_reluZ;
    const float* ib = in + (size_t)b*CC*LP;
    int t = threadIdx.x;

    for (int e = t; e < 64*3*33; e += 256){
        int ci = e / 99; int rem = e % 99; int r = rem / 33; int c2 = rem % 33;
        *(float2*)&s[(ci*3 + r)*68 + c2*2] =
            *(const float2*)&ib[(size_t)ci*LP + (li + r)*PW + c2*2];
    }

    int j0 = (t & 15)*4, c0 = (t >> 4)*4;
    float acc[4][4];
    #pragma unroll
    for (int i = 0; i < 4; i++)
        #pragma unroll
        for (int j = 0; j < 4; j++) acc[i][j] = 0.f;

    for (int cc = 0; cc < 4; cc++){
        __syncthreads();
        for (int e = t; e < 9216; e += 256)
            wsm[e] = w[(e / 144)*576 + cc*144 + (e % 144)];
        __syncthreads();
        #pragma unroll 2
        for (int cil = 0; cil < 16; cil++){
            const float* sr = &s[(cc*16 + cil)*3*68];
            float p[3][6];
            #pragma unroll
            for (int r = 0; r < 3; r++){
                float4 u = *(const float4*)&sr[r*68 + j0];
                float2 v = *(const float2*)&sr[r*68 + j0 + 4];
                p[r][0]=u.x; p[r][1]=u.y; p[r][2]=u.z; p[r][3]=u.w; p[r][4]=v.x; p[r][5]=v.y;
            }
            #pragma unroll
            for (int i = 0; i < 4; i++){
                const float* wp = &wsm[(c0 + i)*144 + cil*9];
                float w0=wp[0],w1=wp[1],w2=wp[2],w3=wp[3],w4=wp[4],
                      w5=wp[5],w6=wp[6],w7=wp[7],w8=wp[8];
                #pragma unroll
                for (int j = 0; j < 4; j++)
                    acc[i][j] += p[0][j]*w0 + p[0][j+1]*w1 + p[0][j+2]*w2
                               + p[1][j]*w3 + p[1][j+1]*w4 + p[1][j+2]*w5
                               + p[2][j]*w6 + p[2][j+1]*w7 + p[2][j+2]*w8;
            }
        }
    }

    float bv[4];
    #pragma unroll
    for (int i = 0; i < 4; i++) bv[i] = __ldg(&bias[c0 + i]);
    if (mode == 0){
        #pragma unroll
        for (int i = 0; i < 4; i++)
            #pragma unroll
            for (int j = 0; j < 4; j++)
                g_reluZ[(size_t)(b*CC + c0 + i)*LP + (li + 1)*PW + (j0 + j + 1)] =
                    fmaxf(acc[i][j] + bv[i], 0.f);
    } else {
        #pragma unroll
        for (int i = 0; i < 4; i++){
            float4 o = make_float4(acc[i][0]+bv[i], acc[i][1]+bv[i],
                                   acc[i][2]+bv[i], acc[i][3]+bv[i]);
            *(float4*)&g_feature[((b*CC + c0 + i)*HH + li)*WW + j0] = o;
        }
    }
}

// ---------------- K3: pixel gram GEMM, symmetric-halved ----------------
// Only tiles pt<=qt. Off-diagonal blocks also write the transposed tile via
// a pitch-133 smem stage (coalesced STG.128 on the transposed side).
__global__ __launch_bounds__(256, 2) void gram_gemm(){
    extern __shared__ float sg[];
    float* Qs    = sg;            // [64][128]
    float* Ks    = sg + 8192;     // [64][128]
    float* stage = sg;            // alias: [128][133]
    int sIdx = blockIdx.x, b = blockIdx.y;
    int qt = (int)((sqrtf(8.f*sIdx + 1.f) - 1.f)*0.5f);
    while ((qt + 1)*(qt + 2)/2 <= sIdx) qt++;
    while (qt*(qt + 1)/2 > sIdx) qt--;
    int pt = sIdx - qt*(qt + 1)/2;
    int p0 = pt*128, q0 = qt*128;
    int t = threadIdx.x, ty = t >> 4, tx = t & 15;
    const float* xp = &g_xpadR[(size_t)b*CC*LP];

    for (int e = t; e < 64*128; e += 256){
        int d = e >> 7, col = e & 127;
        int p = p0 + col, q = q0 + col;
        Qs[e] = (p < LP) ? xp[(size_t)d*LP + p] : 0.f;
        Ks[e] = (q < LP) ? xp[(size_t)d*LP + q] : 0.f;
    }
    __syncthreads();

    float acc[8][8];
    #pragma unroll
    for (int i = 0; i < 8; i++)
        #pragma unroll
        for (int j = 0; j < 8; j++) acc[i][j] = 0.f;

    #pragma unroll 4
    for (int d = 0; d < 64; d++){
        float4 a0 = *(const float4*)&Qs[d*128 + ty*4];
        float4 a1 = *(const float4*)&Qs[d*128 + 64 + ty*4];
        float4 b0 = *(const float4*)&Ks[d*128 + tx*4];
        float4 b1 = *(const float4*)&Ks[d*128 + 64 + tx*4];
        float ar[8] = {a0.x,a0.y,a0.z,a0.w,a1.x,a1.y,a1.z,a1.w};
        float br[8] = {b0.x,b0.y,b0.z,b0.w,b1.x,b1.y,b1.z,b1.w};
        #pragma unroll
        for (int i = 0; i < 8; i++)
            #pragma unroll
            for (int j = 0; j < 8; j++) acc[i][j] += ar[i]*br[j];
    }

    float* Gb = &g_G[(size_t)b*LP*LP];
    // direct tile write (rows p, cols q)
    #pragma unroll
    for (int i = 0; i < 8; i++){
        int p = p0 + ((i < 4) ? (ty*4 + i) : (64 + ty*4 + i - 4));
        if (p >= LP) continue;
        #pragma unroll
        for (int half = 0; half < 2; half++){
            int q = q0 + half*64 + tx*4;
            if (q + 4 <= LP){
                float4 v = make_float4(acc[i][half*4], acc[i][half*4+1],
                                       acc[i][half*4+2], acc[i][half*4+3]);
                *(float4*)&Gb[(size_t)p*LP + q] = v;
            } else {
                for (int j = 0; j < 4; j++)
                    if (q + j < LP) Gb[(size_t)p*LP + q + j] = acc[i][half*4 + j];
            }
        }
    }

    if (pt != qt){
        __syncthreads();                 // Qs/Ks dead; reuse as stage
        #pragma unroll
        for (int i = 0; i < 8; i++){
            int pl = (i < 4) ? (ty*4 + i) : (64 + ty*4 + i - 4);
            #pragma unroll
            for (int j = 0; j < 8; j++){
                int ql = (j < 4) ? (tx*4 + j) : (64 + tx*4 + j - 4);
                stage[pl*133 + ql] = acc[i][j];
            }
        }
        __syncthreads();
        int wid = t >> 5, lane = t & 31;
        for (int r = wid; r < 128; r += 8){
            int q = q0 + r;
            if (q < LP){
                float4 o;
                o.x = stage[(lane*4 + 0)*133 + r];
                o.y = stage[(lane*4 + 1)*133 + r];
                o.z = stage[(lane*4 + 2)*133 + r];
                o.w = stage[(lane*4 + 3)*133 + r];
                *(float4*)&Gb[(size_t)q*LP + p0 + lane*4] = o;  // pt<=33 -> p in range
            }
        }
    }
}

// ---------------- K4: reciprocal patch norms from diag(G) ----------------
__global__ void rn_kernel(){
    int b = blockIdx.y, li = blockIdx.x, lj = threadIdx.x;   // 64 threads
    const float* Gb = &g_G[(size_t)b*LP*LP];
    float s = 0.f;
    #pragma unroll
    for (int kh = 0; kh < 3; kh++)
        #pragma unroll
        for (int kw = 0; kw < 3; kw++){
            int p = (li + kh)*PW + lj + kw;
            s += Gb[(size_t)p*LP + p];
        }
    g_rn[b*LL + li*64 + lj] = 1.0f / fmaxf(sqrtf(s), 1e-12f);
}

// ---------------- K5: 9-shift sums of G, scaled; parallel streaming top-5 ----------------
__global__ __launch_bounds__(256, 3) void stopk_kernel(){
    extern __shared__ float sm[];
    float* Bs  = sm;                 // [3][66][68] = 13464 floats
    float* rnq = sm + 13464;         // [64]
    float* rnk = rnq + 64;           // [64]
    float* Sc  = sm;                 // alias, used after Bs consumed

    int b  = blockIdx.x >> 6;
    int li = blockIdx.x & 63;
    int t  = threadIdx.x, ty = t >> 4, tx = t & 15;
    int tr = t >> 5, tc2 = t & 31;
    int qq = t & 63, seg = t >> 6;   // scan role: query qq, key segment seg

    if (t < 64) rnq[t] = g_rn[b*LL + li*64 + t];

    float tv[5]; int tix[5];
    #pragma unroll
    for (int i = 0; i < 5; i++){ tv[i] = -1e30f; tix[i] = 0; }

    const float* growbase = &g_G[(size_t)b*LP*LP] + (size_t)(li*PW)*LP;

    for (int mi = 0; mi < 64; mi++){
        __syncthreads();
        if (t < 64) rnk[t] = g_rn[b*LL + mi*64 + t];
        #pragma unroll
        for (int pass = 0; pass < 25; pass++){
            int row = pass*8 + tr;
            if (row < 198){
                int kh = (row >= 132) ? 2 : ((row >= 66) ? 1 : 0);
                const float2 v = *(const float2*)(growbase + (size_t)row*LP + (mi + kh)*PW + tc2*2);
                *(float2*)&Bs[row*68 + tc2*2] = v;
            }
        }
        if (t < 198){
            int row = t;
            int kh = (row >= 132) ? 2 : ((row >= 66) ? 1 : 0);
            const float2 v = *(const float2*)(growbase + (size_t)row*LP + (mi + kh)*PW + 64);
            *(float2*)&Bs[row*68 + 64] = v;
        }
        __syncthreads();

        int lj0 = ty*4, mj0 = tx*4;
        float S[4][4];
        #pragma unroll
        for (int i = 0; i < 4; i++)
            #pragma unroll
            for (int j = 0; j < 4; j++) S[i][j] = 0.f;

        #pragma unroll
        for (int kh = 0; kh < 3; kh++){
            float wv[6][6];
            #pragma unroll
            for (int r = 0; r < 6; r++){
                float4 u = *(const float4*)&Bs[(kh*66 + lj0 + r)*68 + mj0];
                float2 v = *(const float2*)&Bs[(kh*66 + lj0 + r)*68 + mj0 + 4];
                wv[r][0]=u.x; wv[r][1]=u.y; wv[r][2]=u.z; wv[r][3]=u.w; wv[r][4]=v.x; wv[r][5]=v.y;
            }
            #pragma unroll
            for (int kw = 0; kw < 3; kw++)
                #pragma unroll
                for (int i = 0; i < 4; i++)
                    #pragma unroll
                    for (int j = 0; j < 4; j++)
                        S[i][j] += wv[i+kw][j+kw];
        }
        __syncthreads();   // Bs reads done; safe to alias as Sc

        #pragma unroll
        for (int i = 0; i < 4; i++){
            float rq = rnq[lj0 + i];
            #pragma unroll
            for (int j = 0; j < 4; j++)
                Sc[(lj0 + i)*65 + mj0 + j] = S[i][j] * rq * rnk[mj0 + j];
        }
        __syncthreads();

        {   // all 256 threads scan: query qq, keys [seg*16, seg*16+16)
            const float* rowp = &Sc[qq*65 + seg*16];
            int k0 = (mi << 6) + seg*16;
            for (int jj = 0; jj < 16; jj++){
                float s = rowp[jj];
                if (s > tv[4]){
                    float v0 = s; int i0 = k0 + jj;
                    #pragma unroll
                    for (int p = 0; p < 5; p++){
                        if (v0 > tv[p]){
                            float tpv = tv[p]; int tpi = tix[p];
                            tv[p] = v0; tix[p] = i0;
                            v0 = tpv; i0 = tpi;
                        }
                    }
                }
            }
        }
    }

    // ---- merge 4 segment lists per query, exact (value desc, index asc) ----
    __syncthreads();
    float* mv = sm;                   // [64][20]
    int*   mx = (int*)(sm + 1280);    // [64][20]
    #pragma unroll
    for (int r = 0; r < 5; r++){
        mv[qq*20 + seg*5 + r] = tv[r];
        mx[qq*20 + seg*5 + r] = tix[r];
    }
    __syncthreads();
    if (t < 64){
        unsigned used = 0;
        int l = li*64 + t;
        for (int r = 0; r < 5; r++){
            float bvv = -3e38f; int bii = 0x7fffffff; int bc = 0;
            #pragma unroll
            for (int c = 0; c < 20; c++){
                if (used & (1u << c)) continue;
                float v = mv[t*20 + c]; int ii = mx[t*20 + c];
                if (v > bvv || (v == bvv && ii < bii)){ bvv = v; bii = ii; bc = c; }
            }
            used |= 1u << bc;
            if (r >= 1){
                g_topv[(b*4 + (r-1))*LL + l] = bvv;
                g_topi[(b*4 + (r-1))*LL + l] = bii;
            }
        }
    }
}

// ---------------- K6: gather+fold texture, 1x1 convs, final output ----------------
__global__ __launch_bounds__(256, 2) void final_kernel(const float* __restrict__ x,
                             const float* __restrict__ wt1, const float* __restrict__ bt1,
                             const float* __restrict__ wt2, const float* __restrict__ bt2,
                             float* __restrict__ out){
    extern __shared__ float sm[];
    float* Tc   = sm;                    // [256][64] (later aliased as fx[128][64])
    float* tex  = sm + 16384;            // [64][64]
    float* wbuf = sm + 20480;            // [64][64] staged weight chunk
    float* msc  = sm + 24576;            // [4][64]
    int*   midx = (int*)(sm + 24832);    // [4][3][64]
    int b = blockIdx.x >> 6, i = blockIdx.x & 63;
    int t = threadIdx.x;
    int j0 = (t & 15)*4, c0 = (t >> 4)*4;

    for (int e = t; e < 4*3*64; e += 256){
        int br = e / 192, rr = (e / 64) % 3, j = e & 63;
        int li = i - 1 + rr;
        int v = 0;
        if ((unsigned)li < 64u) v = g_topi[(b*4 + br)*LL + li*64 + j];
        midx[e] = v;
    }
    { int br = t >> 6, j = t & 63; msc[t] = g_topv[(b*4 + br)*LL + i*64 + j]; }
    __syncthreads();

    const float* xp = &g_xpadR[(size_t)b*CC*LP];
    for (int e = t; e < 256*64; e += 256){
        int ci = e >> 6, j = e & 63;
        int br = ci >> 6, c = ci & 63;
        const float* xpc = xp + c*LP;
        float sum = 0.f;
        #pragma unroll
        for (int kh = 0; kh < 3; kh++){
            int li = i + 1 - kh;
            if ((unsigned)li >= 64u) continue;
            int slot = 2 - kh;
            #pragma unroll
            for (int kw = 0; kw < 3; kw++){
                int lj = j + 1 - kw;
                if ((unsigned)lj >= 64u) continue;
                int m  = midx[br*192 + slot*64 + lj];
                int mi = m >> 6, mj = m & 63;
                sum += xpc[(mi + kh)*PW + mj + kw];
            }
        }
        Tc[e] = sum * msc[br*64 + j] * (1.0f/9.0f);
    }

    // texture = wt1 @ Tcat + bt1  (K=256, staged weight chunks of 64)
    float a[4][4];
    #pragma unroll
    for (int ii = 0; ii < 4; ii++)
        #pragma unroll
        for (int j = 0; j < 4; j++) a[ii][j] = 0.f;
    for (int cc = 0; cc < 4; cc++){
        __syncthreads();
        for (int e = t; e < 4096; e += 256)
            wbuf[e] = wt1[(e >> 6)*256 + cc*64 + (e & 63)];
        __syncthreads();
        #pragma unroll 4
        for (int cil = 0; cil < 64; cil++){
            float4 v = *(const float4*)&Tc[(cc*64 + cil)*64 + j0];
            #pragma unroll
            for (int ii = 0; ii < 4; ii++){
                float wv = wbuf[(c0 + ii)*64 + cil];
                a[ii][0] += wv*v.x; a[ii][1] += wv*v.y; a[ii][2] += wv*v.z; a[ii][3] += wv*v.w;
            }
        }
    }
    #pragma unroll
    for (int ii = 0; ii < 4; ii++){
        float bv = __ldg(&bt1[c0 + ii]);
        float4 o = make_float4(a[ii][0]+bv, a[ii][1]+bv, a[ii][2]+bv, a[ii][3]+bv);
        *(float4*)&tex[(c0 + ii)*64 + j0] = o;
    }
    __syncthreads();

    // load feature & x rows into Tc region (Tc dead)
    float* fx = Tc;
    for (int e = t; e < 64*64; e += 256){
        int cch = e >> 6, j = e & 63;
        fx[e]         = g_feature[((b*CC + cch)*HH + i)*WW + j];
        fx[64*64 + e] = x[((b*CC + cch)*HH + i)*WW + j];
    }

    // y = wt2 @ [feature; x; texture] + bt2  (K=192, 3 chunks)
    float a2[4][4];
    #pragma unroll
    for (int ii = 0; ii < 4; ii++)
        #pragma unroll
        for (int j = 0; j < 4; j++) a2[ii][j] = 0.f;
    for (int cc = 0; cc < 3; cc++){
        __syncthreads();
        for (int e = t; e < 4096; e += 256)
            wbuf[e] = wt2[(e >> 6)*192 + cc*64 + (e & 63)];
        __syncthreads();
        const float* src = (cc == 2) ? tex : fx + cc*4096;
        #pragma unroll 4
        for (int cil = 0; cil < 64; cil++){
            float4 v = *(const float4*)&src[cil*64 + j0];
            #pragma unroll
            for (int ii = 0; ii < 4; ii++){
                float wv = wbuf[(c0 + ii)*64 + cil];
                a2[ii][0] += wv*v.x; a2[ii][1] += wv*v.y; a2[ii][2] += wv*v.z; a2[ii][3] += wv*v.w;
            }
        }
    }
    #pragma unroll
    for (int ii = 0; ii < 4; ii++){
        float bv = __ldg(&bt2[c0 + ii]);
        float4 o = make_float4(a2[ii][0]+bv, a2[ii][1]+bv, a2[ii][2]+bv, a2[ii][3]+bv);
        *(float4*)&out[((b*CC + c0 + ii)*HH + i)*WW + j0] = o;
    }
}

// ---------------- launch ----------------
extern "C" void kernel_launch(void* const* d_in, const int* in_sizes, int n_in,
                              void* d_out, int out_size){
    const float* x   = (const float*)d_in[0];
    const float* w1  = (const float*)d_in[1];
    const float* b1  = (const float*)d_in[2];
    const float* w2  = (const float*)d_in[3];
    const float* b2  = (const float*)d_in[4];
    const float* wt1 = (const float*)d_in[5];
    const float* bt1 = (const float*)d_in[6];
    const float* wt2 = (const float*)d_in[7];
    const float* bt2 = (const float*)d_in[8];
    float* out = (float*)d_out;

    const int CONV_SMEM = (13056 + 9216)*4;    // 89088
    const int GEMM_SMEM = 128*133*4;           // 68096
    const int STK_SMEM  = (13464 + 128)*4;     // 54368
    const int FIN_SMEM  = 25600*4;             // 102400
    cudaFuncSetAttribute(convg_kernel, cudaFuncAttributeMaxDynamicSharedMemorySize, CONV_SMEM);
    cudaFuncSetAttribute(gram_gemm,    cudaFuncAttributeMaxDynamicSharedMemorySize, GEMM_SMEM);
    cudaFuncSetAttribute(stopk_kernel, cudaFuncAttributeMaxDynamicSharedMemorySize, STK_SMEM);
    cudaFuncSetAttribute(final_kernel, cudaFuncAttributeMaxDynamicSharedMemorySize, FIN_SMEM);

    pad_kernel<<<dim3(66, 4), 256>>>(x);
    gram_gemm<<<dim3(630, 4), 256, GEMM_SMEM>>>();
    convg_kernel<<<dim3(64, 4), 256, CONV_SMEM>>>(w1, b1, 0);
    convg_kernel<<<dim3(64, 4), 256, CONV_SMEM>>>(w2, b2, 1);
    rn_kernel<<<dim3(64, 4), 64>>>();
    stopk_kernel<<<256, 256, STK_SMEM>>>();
    final_kernel<<<256, 256, FIN_SMEM>>>(x, wt1, bt1, wt2, bt2, out);
}

// round 5
// speedup vs baseline: 5.0469x; 1.0162x over previous
#include <cuda_runtime.h>
#include <math.h>

#define BB 4
#define CC 64
#define HH 64
#define WW 64
#define LL 4096      // H*W
#define PW 66        // padded width/height
#define LP 4356      // 66*66 padded pixels

// ---------------- persistent device scratch ----------------
__device__ __align__(16) float g_xpadR[BB*CC*LP];     // reflect-padded x
__device__ __align__(16) float g_xpadZ[BB*CC*LP];     // zero-padded x (borders stay 0)
__device__ __align__(16) float g_reluZ[BB*CC*LP];     // zero-padded relu(conv1)
__device__ __align__(16) float g_G[(size_t)BB*LP*LP]; // pixel gram, 303.6 MB
__device__ float g_rn[BB*LL];                         // reciprocal patch norms
__device__ float g_feature[BB*CC*HH*WW];
__device__ float g_topv[BB*4*LL];
__device__ int   g_topi[BB*4*LL];
__device__ float g_pmv[BB*4*5*LL];                    // split-K partial top-5 values
__device__ int   g_pmi[BB*4*5*LL];                    // split-K partial top-5 indices

__device__ __forceinline__ int refl(int t){ return t < 0 ? -t : (t >= 64 ? 126 - t : t); }

// ---------------- K1: build reflect- and zero-padded inputs ----------------
__global__ void pad_kernel(const float* __restrict__ x){
    int b  = blockIdx.y;
    int pr = blockIdx.x;                 // 0..65
    int sr = refl(pr - 1);
    bool rin = (pr >= 1 && pr <= 64);
    for (int e = threadIdx.x; e < CC*PW; e += blockDim.x){
        int c = e / PW, pc = e % PW;
        int sc = refl(pc - 1);
        float v = x[((b*CC + c)*HH + sr)*WW + sc];
        g_xpadR[(b*CC + c)*LP + pr*PW + pc] = v;
        if (rin && pc >= 1 && pc <= 64)
            g_xpadZ[(b*CC + c)*LP + pr*PW + pc] = v;
    }
}

// ---------------- K2: 3x3 conv (zero pad), co-split x2 ----------------
// Block = (row, batch, co-half). 256 threads: thread = 2 co x 4 pixels.
__global__ __launch_bounds__(256, 3) void convg_kernel(const float* __restrict__ w,
                                                       const float* __restrict__ bias,
                                                       int mode){
    extern __shared__ float cs[];
    float* s   = cs;            // [64][3][68] = 13056 floats
    float* wsm = cs + 13056;    // [32co][16ci][9] = 4608 floats
    int li = blockIdx.x, b = blockIdx.y, coh = blockIdx.z;
    const float* in = (mode == 0) ? g_xpadZ : g_reluZ;
    const float* ib = in + (size_t)b*CC*LP;
    int t = threadIdx.x;

    for (int e = t; e < 64*3*33; e += 256){
        int ci = e / 99; int rem = e % 99; int r = rem / 33; int c2 = rem % 33;
        *(float2*)&s[(ci*3 + r)*68 + c2*2] =
            *(const float2*)&ib[(size_t)ci*LP + (li + r)*PW + c2*2];
    }

    int j0 = (t & 15)*4, c0l = (t >> 4)*2;
    float acc[2][4];
    #pragma unroll
    for (int i = 0; i < 2; i++)
        #pragma unroll
        for (int j = 0; j < 4; j++) acc[i][j] = 0.f;

    for (int cc = 0; cc < 4; cc++){
        __syncthreads();
        for (int e = t; e < 4608; e += 256)
            wsm[e] = w[(coh*32 + e/144)*576 + cc*144 + (e % 144)];
        __syncthreads();
        #pragma unroll 2
        for (int cil = 0; cil < 16; cil++){
            const float* sr = &s[(cc*16 + cil)*3*68];
            float p[3][6];
            #pragma unroll
            for (int r = 0; r < 3; r++){
                float4 u = *(const float4*)&sr[r*68 + j0];
                float2 v = *(const float2*)&sr[r*68 + j0 + 4];
                p[r][0]=u.x; p[r][1]=u.y; p[r][2]=u.z; p[r][3]=u.w; p[r][4]=v.x; p[r][5]=v.y;
            }
            #pragma unroll
            for (int i = 0; i < 2; i++){
                const float* wp = &wsm[(c0l + i)*144 + cil*9];
                float w0=wp[0],w1=wp[1],w2=wp[2],w3=wp[3],w4=wp[4],
                      w5=wp[5],w6=wp[6],w7=wp[7],w8=wp[8];
                #pragma unroll
                for (int j = 0; j < 4; j++)
                    acc[i][j] += p[0][j]*w0 + p[0][j+1]*w1 + p[0][j+2]*w2
                               + p[1][j]*w3 + p[1][j+1]*w4 + p[1][j+2]*w5
                               + p[2][j]*w6 + p[2][j+1]*w7 + p[2][j+2]*w8;
            }
        }
    }

    #pragma unroll
    for (int i = 0; i < 2; i++){
        int co = coh*32 + c0l + i;
        float bv = __ldg(&bias[co]);
        if (mode == 0){
            #pragma unroll
            for (int j = 0; j < 4; j++)
                g_reluZ[(size_t)(b*CC + co)*LP + (li + 1)*PW + (j0 + j + 1)] =
                    fmaxf(acc[i][j] + bv, 0.f);
        } else {
            float4 o = make_float4(acc[i][0]+bv, acc[i][1]+bv,
                                   acc[i][2]+bv, acc[i][3]+bv);
            *(float4*)&g_feature[((b*CC + co)*HH + li)*WW + j0] = o;
        }
    }
}

// ---------------- K3: pixel gram GEMM, symmetric-halved ----------------
__global__ __launch_bounds__(256, 2) void gram_gemm(){
    extern __shared__ float sg[];
    float* Qs    = sg;            // [64][128]
    float* Ks    = sg + 8192;     // [64][128]
    float* stage = sg;            // alias: [128][133]
    int sIdx = blockIdx.x, b = blockIdx.y;
    int qt = (int)((sqrtf(8.f*sIdx + 1.f) - 1.f)*0.5f);
    while ((qt + 1)*(qt + 2)/2 <= sIdx) qt++;
    while (qt*(qt + 1)/2 > sIdx) qt--;
    int pt = sIdx - qt*(qt + 1)/2;
    int p0 = pt*128, q0 = qt*128;
    int t = threadIdx.x, ty = t >> 4, tx = t & 15;
    const float* xp = &g_xpadR[(size_t)b*CC*LP];

    for (int e = t; e < 64*128; e += 256){
        int d = e >> 7, col = e & 127;
        int p = p0 + col, q = q0 + col;
        Qs[e] = (p < LP) ? xp[(size_t)d*LP + p] : 0.f;
        Ks[e] = (q < LP) ? xp[(size_t)d*LP + q] : 0.f;
    }
    __syncthreads();

    float acc[8][8];
    #pragma unroll
    for (int i = 0; i < 8; i++)
        #pragma unroll
        for (int j = 0; j < 8; j++) acc[i][j] = 0.f;

    #pragma unroll 4
    for (int d = 0; d < 64; d++){
        float4 a0 = *(const float4*)&Qs[d*128 + ty*4];
        float4 a1 = *(const float4*)&Qs[d*128 + 64 + ty*4];
        float4 b0 = *(const float4*)&Ks[d*128 + tx*4];
        float4 b1 = *(const float4*)&Ks[d*128 + 64 + tx*4];
        float ar[8] = {a0.x,a0.y,a0.z,a0.w,a1.x,a1.y,a1.z,a1.w};
        float br[8] = {b0.x,b0.y,b0.z,b0.w,b1.x,b1.y,b1.z,b1.w};
        #pragma unroll
        for (int i = 0; i < 8; i++)
            #pragma unroll
            for (int j = 0; j < 8; j++) acc[i][j] += ar[i]*br[j];
    }

    float* Gb = &g_G[(size_t)b*LP*LP];
    #pragma unroll
    for (int i = 0; i < 8; i++){
        int p = p0 + ((i < 4) ? (ty*4 + i) : (64 + ty*4 + i - 4));
        if (p >= LP) continue;
        #pragma unroll
        for (int half = 0; half < 2; half++){
            int q = q0 + half*64 + tx*4;
            if (q + 4 <= LP){
                float4 v = make_float4(acc[i][half*4], acc[i][half*4+1],
                                       acc[i][half*4+2], acc[i][half*4+3]);
                *(float4*)&Gb[(size_t)p*LP + q] = v;
            } else {
                for (int j = 0; j < 4; j++)
                    if (q + j < LP) Gb[(size_t)p*LP + q + j] = acc[i][half*4 + j];
            }
        }
    }

    if (pt != qt){
        __syncthreads();
        #pragma unroll
        for (int i = 0; i < 8; i++){
            int pl = (i < 4) ? (ty*4 + i) : (64 + ty*4 + i - 4);
            #pragma unroll
            for (int j = 0; j < 8; j++){
                int ql = (j < 4) ? (tx*4 + j) : (64 + tx*4 + j - 4);
                stage[pl*133 + ql] = acc[i][j];
            }
        }
        __syncthreads();
        int wid = t >> 5, lane = t & 31;
        for (int r = wid; r < 128; r += 8){
            int q = q0 + r;
            if (q < LP){
                float4 o;
                o.x = stage[(lane*4 + 0)*133 + r];
                o.y = stage[(lane*4 + 1)*133 + r];
                o.z = stage[(lane*4 + 2)*133 + r];
                o.w = stage[(lane*4 + 3)*133 + r];
                *(float4*)&Gb[(size_t)q*LP + p0 + lane*4] = o;
            }
        }
    }
}

// ---------------- K4: reciprocal patch norms from diag(G) ----------------
__global__ void rn_kernel(){
    int b = blockIdx.y, li = blockIdx.x, lj = threadIdx.x;   // 64 threads
    const float* Gb = &g_G[(size_t)b*LP*LP];
    float s = 0.f;
    #pragma unroll
    for (int kh = 0; kh < 3; kh++)
        #pragma unroll
        for (int kw = 0; kw < 3; kw++){
            int p = (li + kh)*PW + lj + kw;
            s += Gb[(size_t)p*LP + p];
        }
    g_rn[b*LL + li*64 + lj] = 1.0f / fmaxf(sqrtf(s), 1e-12f);
}

// ---------------- K5a: split-K top-5 (each block scans 16 key tiles) ----------------
__global__ __launch_bounds__(256, 3) void stopk_part(){
    extern __shared__ float sm[];
    float* Bs  = sm;                 // [3][66][68] = 13464 floats
    float* rnq = sm + 13464;         // [64]
    float* rnk = rnq + 64;           // [64]
    float* Sc  = sm;                 // alias

    int b  = blockIdx.x >> 6;
    int li = blockIdx.x & 63;
    int sp = blockIdx.y;             // 0..3
    int t  = threadIdx.x, ty = t >> 4, tx = t & 15;
    int tr = t >> 5, tc2 = t & 31;
    int qq = t & 63, seg = t >> 6;

    if (t < 64) rnq[t] = g_rn[b*LL + li*64 + t];

    float tv[5]; int tix[5];
    #pragma unroll
    for (int i = 0; i < 5; i++){ tv[i] = -1e30f; tix[i] = 0; }

    const float* growbase = &g_G[(size_t)b*LP*LP] + (size_t)(li*PW)*LP;

    for (int mi = sp*16; mi < sp*16 + 16; mi++){
        __syncthreads();
        if (t < 64) rnk[t] = g_rn[b*LL + mi*64 + t];
        #pragma unroll
        for (int pass = 0; pass < 25; pass++){
            int row = pass*8 + tr;
            if (row < 198){
                int kh = (row >= 132) ? 2 : ((row >= 66) ? 1 : 0);
                const float2 v = *(const float2*)(growbase + (size_t)row*LP + (mi + kh)*PW + tc2*2);
                *(float2*)&Bs[row*68 + tc2*2] = v;
            }
        }
        if (t < 198){
            int row = t;
            int kh = (row >= 132) ? 2 : ((row >= 66) ? 1 : 0);
            const float2 v = *(const float2*)(growbase + (size_t)row*LP + (mi + kh)*PW + 64);
            *(float2*)&Bs[row*68 + 64] = v;
        }
        __syncthreads();

        int lj0 = ty*4, mj0 = tx*4;
        float S[4][4];
        #pragma unroll
        for (int i = 0; i < 4; i++)
            #pragma unroll
            for (int j = 0; j < 4; j++) S[i][j] = 0.f;

        #pragma unroll
        for (int kh = 0; kh < 3; kh++){
            float wv[6][6];
            #pragma unroll
            for (int r = 0; r < 6; r++){
                float4 u = *(const float4*)&Bs[(kh*66 + lj0 + r)*68 + mj0];
                float2 v = *(const float2*)&Bs[(kh*66 + lj0 + r)*68 + mj0 + 4];
                wv[r][0]=u.x; wv[r][1]=u.y; wv[r][2]=u.z; wv[r][3]=u.w; wv[r][4]=v.x; wv[r][5]=v.y;
            }
            #pragma unroll
            for (int kw = 0; kw < 3; kw++)
                #pragma unroll
                for (int i = 0; i < 4; i++)
                    #pragma unroll
                    for (int j = 0; j < 4; j++)
                        S[i][j] += wv[i+kw][j+kw];
        }
        __syncthreads();

        #pragma unroll
        for (int i = 0; i < 4; i++){
            float rq = rnq[lj0 + i];
            #pragma unroll
            for (int j = 0; j < 4; j++)
                Sc[(lj0 + i)*65 + mj0 + j] = S[i][j] * rq * rnk[mj0 + j];
        }
        __syncthreads();

        {   // all 256 threads: query qq, keys [seg*16, seg*16+16)
            const float* rowp = &Sc[qq*65 + seg*16];
            int k0 = (mi << 6) + seg*16;
            for (int jj = 0; jj < 16; jj++){
                float s = rowp[jj];
                if (s > tv[4]){
                    float v0 = s; int i0 = k0 + jj;
                    #pragma unroll
                    for (int p = 0; p < 5; p++){
                        if (v0 > tv[p]){
                            float tpv = tv[p]; int tpi = tix[p];
                            tv[p] = v0; tix[p] = i0;
                            v0 = tpv; i0 = tpi;
                        }
                    }
                }
            }
        }
    }

    // merge 4 segment lists per query (exact value-desc, index-asc), store top-5
    __syncthreads();
    float* mv = sm;                   // [64][20]
    int*   mx = (int*)(sm + 1280);    // [64][20]
    #pragma unroll
    for (int r = 0; r < 5; r++){
        mv[qq*20 + seg*5 + r] = tv[r];
        mx[qq*20 + seg*5 + r] = tix[r];
    }
    __syncthreads();
    if (t < 64){
        unsigned used = 0;
        int l = li*64 + t;
        for (int r = 0; r < 5; r++){
            float bvv = -3e38f; int bii = 0x7fffffff; int bc = 0;
            #pragma unroll
            for (int c = 0; c < 20; c++){
                if (used & (1u << c)) continue;
                float v = mv[t*20 + c]; int ii = mx[t*20 + c];
                if (v > bvv || (v == bvv && ii < bii)){ bvv = v; bii = ii; bc = c; }
            }
            used |= 1u << bc;
            g_pmv[((b*4 + sp)*5 + r)*LL + l] = bvv;
            g_pmi[((b*4 + sp)*5 + r)*LL + l] = bii;
        }
    }
}

// ---------------- K5b: merge 4 split lists into final ranks 1..4 ----------------
__global__ void topk_merge(){
    int b = blockIdx.y, li = blockIdx.x, q = threadIdx.x;  // 64 threads
    int l = li*64 + q;
    float mv[20]; int mx[20];
    #pragma unroll
    for (int sp = 0; sp < 4; sp++)
        #pragma unroll
        for (int r = 0; r < 5; r++){
            mv[sp*5 + r] = g_pmv[((b*4 + sp)*5 + r)*LL + l];
            mx[sp*5 + r] = g_pmi[((b*4 + sp)*5 + r)*LL + l];
        }
    unsigned used = 0;
    for (int r = 0; r < 5; r++){
        float bvv = -3e38f; int bii = 0x7fffffff; int bc = 0;
        #pragma unroll
        for (int c = 0; c < 20; c++){
            if (used & (1u << c)) continue;
            if (mv[c] > bvv || (mv[c] == bvv && mx[c] < bii)){ bvv = mv[c]; bii = mx[c]; bc = c; }
        }
        used |= 1u << bc;
        if (r >= 1){
            g_topv[(b*4 + (r-1))*LL + l] = bvv;
            g_topi[(b*4 + (r-1))*LL + l] = bii;
        }
    }
}

// ---------------- K6: gather+fold texture, 1x1 convs, pixel-split x2 ----------------
__global__ __launch_bounds__(256, 3) void final_kernel(const float* __restrict__ x,
                             const float* __restrict__ wt1, const float* __restrict__ bt1,
                             const float* __restrict__ wt2, const float* __restrict__ bt2,
                             float* __restrict__ out){
    extern __shared__ float sm[];
    float* Tc   = sm;                    // [256][32] (later aliased as fx[128][32])
    float* tex  = sm + 8192;             // [64][32]
    float* wbuf = sm + 10240;            // [64][64]
    float* msc  = sm + 14336;            // [4][32]
    int*   midx = (int*)(sm + 14464);    // [4][3][34]
    int b = blockIdx.x >> 6, i = blockIdx.x & 63;
    int h = blockIdx.y;                  // pixel half
    int t = threadIdx.x;
    int j0 = (t & 15)*2, c0 = (t >> 4)*4;

    for (int e = t; e < 4*3*34; e += 256){
        int br = e / 102, rr = (e / 34) % 3, jo = e % 34;
        int li = i - 1 + rr, lj = h*32 - 1 + jo;
        int v = 0;
        if ((unsigned)li < 64u && (unsigned)lj < 64u)
            v = g_topi[(b*4 + br)*LL + li*64 + lj];
        midx[e] = v;
    }
    if (t < 128){
        int br = t >> 5, j = t & 31;
        msc[t] = g_topv[(b*4 + br)*LL + i*64 + h*32 + j];
    }
    __syncthreads();

    const float* xp = &g_xpadR[(size_t)b*CC*LP];
    for (int e = t; e < 256*32; e += 256){
        int ci = e >> 5, j = e & 31;
        int br = ci >> 6, c = ci & 63;
        int jj = h*32 + j;
        const float* xpc = xp + c*LP;
        float sum = 0.f;
        #pragma unroll
        for (int kh = 0; kh < 3; kh++){
            int li = i + 1 - kh;
            if ((unsigned)li >= 64u) continue;
            int slot = 2 - kh;
            #pragma unroll
            for (int kw = 0; kw < 3; kw++){
                int lj = jj + 1 - kw;
                if ((unsigned)lj >= 64u) continue;
                int jo = lj - h*32 + 1;
                int m  = midx[br*102 + slot*34 + jo];
                int mi = m >> 6, mj = m & 63;
                sum += xpc[(mi + kh)*PW + mj + kw];
            }
        }
        Tc[e] = sum * msc[br*32 + j] * (1.0f/9.0f);
    }

    // texture = wt1 @ Tcat + bt1  (K=256, staged weight chunks of 64)
    float a[4][2];
    #pragma unroll
    for (int ii = 0; ii < 4; ii++){ a[ii][0] = 0.f; a[ii][1] = 0.f; }
    for (int cc = 0; cc < 4; cc++){
        __syncthreads();
        for (int e = t; e < 4096; e += 256)
            wbuf[e] = wt1[(e >> 6)*256 + cc*64 + (e & 63)];
        __syncthreads();
        #pragma unroll 4
        for (int cil = 0; cil < 64; cil++){
            float2 v = *(const float2*)&Tc[(cc*64 + cil)*32 + j0];
            #pragma unroll
            for (int ii = 0; ii < 4; ii++){
                float wv = wbuf[(c0 + ii)*64 + cil];
                a[ii][0] += wv*v.x; a[ii][1] += wv*v.y;
            }
        }
    }
    #pragma unroll
    for (int ii = 0; ii < 4; ii++){
        float bv = __ldg(&bt1[c0 + ii]);
        *(float2*)&tex[(c0 + ii)*32 + j0] = make_float2(a[ii][0]+bv, a[ii][1]+bv);
    }
    __syncthreads();

    // load feature & x half-rows into Tc region (Tc dead)
    float* fx = Tc;
    for (int e = t; e < 64*32; e += 256){
        int cch = e >> 5, j = e & 31;
        fx[e]           = g_feature[((b*CC + cch)*HH + i)*WW + h*32 + j];
        fx[64*32 + e]   = x[((b*CC + cch)*HH + i)*WW + h*32 + j];
    }

    // y = wt2 @ [feature; x; texture] + bt2  (K=192, 3 chunks)
    float a2[4][2];
    #pragma unroll
    for (int ii = 0; ii < 4; ii++){ a2[ii][0] = 0.f; a2[ii][1] = 0.f; }
    for (int cc = 0; cc < 3; cc++){
        __syncthreads();
        for (int e = t; e < 4096; e += 256)
            wbuf[e] = wt2[(e >> 6)*192 + cc*64 + (e & 63)];
        __syncthreads();
        const float* src = (cc == 2) ? tex : fx + cc*2048;
        #pragma unroll 4
        for (int cil = 0; cil < 64; cil++){
            float2 v = *(const float2*)&src[cil*32 + j0];
            #pragma unroll
            for (int ii = 0; ii < 4; ii++){
                float wv = wbuf[(c0 + ii)*64 + cil];
                a2[ii][0] += wv*v.x; a2[ii][1] += wv*v.y;
            }
        }
    }
    #pragma unroll
    for (int ii = 0; ii < 4; ii++){
        float bv = __ldg(&bt2[c0 + ii]);
        *(float2*)&out[((b*CC + c0 + ii)*HH + i)*WW + h*32 + j0] =
            make_float2(a2[ii][0]+bv, a2[ii][1]+bv);
    }
}

// ---------------- launch ----------------
extern "C" void kernel_launch(void* const* d_in, const int* in_sizes, int n_in,
                              void* d_out, int out_size){
    const float* x   = (const float*)d_in[0];
    const float* w1  = (const float*)d_in[1];
    const float* b1  = (const float*)d_in[2];
    const float* w2  = (const float*)d_in[3];
    const float* b2  = (const float*)d_in[4];
    const float* wt1 = (const float*)d_in[5];
    const float* bt1 = (const float*)d_in[6];
    const float* wt2 = (const float*)d_in[7];
    const float* bt2 = (const float*)d_in[8];
    float* out = (float*)d_out;

    const int CONV_SMEM = (13056 + 4608)*4;    // 70656
    const int GEMM_SMEM = 128*133*4;           // 68096
    const int STK_SMEM  = (13464 + 128)*4;     // 54368
    const int FIN_SMEM  = (14464 + 408)*4;     // 59488
    cudaFuncSetAttribute(convg_kernel, cudaFuncAttributeMaxDynamicSharedMemorySize, CONV_SMEM);
    cudaFuncSetAttribute(gram_gemm,    cudaFuncAttributeMaxDynamicSharedMemorySize, GEMM_SMEM);
    cudaFuncSetAttribute(stopk_part,   cudaFuncAttributeMaxDynamicSharedMemorySize, STK_SMEM);
    cudaFuncSetAttribute(final_kernel, cudaFuncAttributeMaxDynamicSharedMemorySize, FIN_SMEM);

    pad_kernel<<<dim3(66, 4), 256>>>(x);
    gram_gemm<<<dim3(630, 4), 256, GEMM_SMEM>>>();
    convg_kernel<<<dim3(64, 4, 2), 256, CONV_SMEM>>>(w1, b1, 0);
    convg_kernel<<<dim3(64, 4, 2), 256, CONV_SMEM>>>(w2, b2, 1);
    rn_kernel<<<dim3(64, 4), 64>>>();
    stopk_part<<<dim3(256, 4), 256, STK_SMEM>>>();
    topk_merge<<<dim3(64, 4), 64>>>();
    final_kernel<<<dim3(256, 2), 256, FIN_SMEM>>>(x, wt1, bt1, wt2, bt2, out);
}

// round 6
// speedup vs baseline: 5.3034x; 1.0508x over previous
#include <cuda_runtime.h>
#include <math.h>

#define BB 4
#define CC 64
#define HH 64
#define WW 64
#define LL 4096      // H*W
#define PW 66        // padded width/height
#define LP 4356      // 66*66 padded pixels

// ---------------- persistent device scratch ----------------
__device__ __align__(16) float g_xpadR[BB*CC*LP];     // reflect-padded x
__device__ __align__(16) float g_xpadZ[BB*CC*LP];     // zero-padded x (borders stay 0)
__device__ __align__(16) float g_reluZ[BB*CC*LP];     // zero-padded relu(conv1)
__device__ __align__(16) float g_G[(size_t)BB*LP*LP]; // pixel gram, 303.6 MB
__device__ float g_rn[BB*LL];                         // reciprocal patch norms
__device__ float g_feature[BB*CC*HH*WW];
__device__ float g_topv[BB*4*LL];
__device__ int   g_topi[BB*4*LL];
__device__ float g_pmv[BB*4*5*LL];                    // split-K partial top-5 values
__device__ int   g_pmi[BB*4*5*LL];                    // split-K partial top-5 indices

__device__ __forceinline__ int refl(int t){ return t < 0 ? -t : (t >= 64 ? 126 - t : t); }

// ---------------- K1: build reflect- and zero-padded inputs ----------------
__global__ void pad_kernel(const float* __restrict__ x){
    int b  = blockIdx.y;
    int pr = blockIdx.x;                 // 0..65
    int sr = refl(pr - 1);
    bool rin = (pr >= 1 && pr <= 64);
    for (int e = threadIdx.x; e < CC*PW; e += blockDim.x){
        int c = e / PW, pc = e % PW;
        int sc = refl(pc - 1);
        float v = x[((b*CC + c)*HH + sr)*WW + sc];
        g_xpadR[(b*CC + c)*LP + pr*PW + pc] = v;
        if (rin && pc >= 1 && pc <= 64)
            g_xpadZ[(b*CC + c)*LP + pr*PW + pc] = v;
    }
}

// ---------------- K2: 3x3 conv (zero pad), round-4 form ----------------
// Block = (output row, batch). 256 threads: thread = 4 co x 4 pixels.
__global__ __launch_bounds__(256, 2) void convg_kernel(const float* __restrict__ w,
                                                       const float* __restrict__ bias,
                                                       int mode){
    extern __shared__ float cs[];
    float* s   = cs;            // [64][3][68] = 13056 floats
    float* wsm = cs + 13056;    // [64co][16ci][9] = 9216 floats
    int li = blockIdx.x, b = blockIdx.y;
    const float* in = (mode == 0) ? g_xpadZ : g_reluZ;
    const float* ib = in + (size_t)b*CC*LP;
    int t = threadIdx.x;

    for (int e = t; e < 64*3*33; e += 256){
        int ci = e / 99; int rem = e % 99; int r = rem / 33; int c2 = rem % 33;
        *(float2*)&s[(ci*3 + r)*68 + c2*2] =
            *(const float2*)&ib[(size_t)ci*LP + (li + r)*PW + c2*2];
    }

    int j0 = (t & 15)*4, c0 = (t >> 4)*4;
    float acc[4][4];
    #pragma unroll
    for (int i = 0; i < 4; i++)
        #pragma unroll
        for (int j = 0; j < 4; j++) acc[i][j] = 0.f;

    for (int cc = 0; cc < 4; cc++){
        __syncthreads();
        for (int e = t; e < 9216; e += 256)
            wsm[e] = w[(e / 144)*576 + cc*144 + (e % 144)];
        __syncthreads();
        #pragma unroll 2
        for (int cil = 0; cil < 16; cil++){
            const float* sr = &s[(cc*16 + cil)*3*68];
            float p[3][6];
            #pragma unroll
            for (int r = 0; r < 3; r++){
                float4 u = *(const float4*)&sr[r*68 + j0];
                float2 v = *(const float2*)&sr[r*68 + j0 + 4];
                p[r][0]=u.x; p[r][1]=u.y; p[r][2]=u.z; p[r][3]=u.w; p[r][4]=v.x; p[r][5]=v.y;
            }
            #pragma unroll
            for (int i = 0; i < 4; i++){
                const float* wp = &wsm[(c0 + i)*144 + cil*9];
                float w0=wp[0],w1=wp[1],w2=wp[2],w3=wp[3],w4=wp[4],
                      w5=wp[5],w6=wp[6],w7=wp[7],w8=wp[8];
                #pragma unroll
                for (int j = 0; j < 4; j++)
                    acc[i][j] += p[0][j]*w0 + p[0][j+1]*w1 + p[0][j+2]*w2
                               + p[1][j]*w3 + p[1][j+1]*w4 + p[1][j+2]*w5
                               + p[2][j]*w6 + p[2][j+1]*w7 + p[2][j+2]*w8;
            }
        }
    }

    float bv[4];
    #pragma unroll
    for (int i = 0; i < 4; i++) bv[i] = __ldg(&bias[c0 + i]);
    if (mode == 0){
        #pragma unroll
        for (int i = 0; i < 4; i++)
            #pragma unroll
            for (int j = 0; j < 4; j++)
                g_reluZ[(size_t)(b*CC + c0 + i)*LP + (li + 1)*PW + (j0 + j + 1)] =
                    fmaxf(acc[i][j] + bv[i], 0.f);
    } else {
        #pragma unroll
        for (int i = 0; i < 4; i++){
            float4 o = make_float4(acc[i][0]+bv[i], acc[i][1]+bv[i],
                                   acc[i][2]+bv[i], acc[i][3]+bv[i]);
            *(float4*)&g_feature[((b*CC + c0 + i)*HH + li)*WW + j0] = o;
        }
    }
}

// ---------------- K3: pixel gram GEMM, symmetric-halved ----------------
__global__ __launch_bounds__(256, 2) void gram_gemm(){
    extern __shared__ float sg[];
    float* Qs    = sg;            // [64][128]
    float* Ks    = sg + 8192;     // [64][128]
    float* stage = sg;            // alias: [128][133]
    int sIdx = blockIdx.x, b = blockIdx.y;
    int qt = (int)((sqrtf(8.f*sIdx + 1.f) - 1.f)*0.5f);
    while ((qt + 1)*(qt + 2)/2 <= sIdx) qt++;
    while (qt*(qt + 1)/2 > sIdx) qt--;
    int pt = sIdx - qt*(qt + 1)/2;
    int p0 = pt*128, q0 = qt*128;
    int t = threadIdx.x, ty = t >> 4, tx = t & 15;
    const float* xp = &g_xpadR[(size_t)b*CC*LP];

    for (int e = t; e < 64*128; e += 256){
        int d = e >> 7, col = e & 127;
        int p = p0 + col, q = q0 + col;
        Qs[e] = (p < LP) ? xp[(size_t)d*LP + p] : 0.f;
        Ks[e] = (q < LP) ? xp[(size_t)d*LP + q] : 0.f;
    }
    __syncthreads();

    float acc[8][8];
    #pragma unroll
    for (int i = 0; i < 8; i++)
        #pragma unroll
        for (int j = 0; j < 8; j++) acc[i][j] = 0.f;

    #pragma unroll 4
    for (int d = 0; d < 64; d++){
        float4 a0 = *(const float4*)&Qs[d*128 + ty*4];
        float4 a1 = *(const float4*)&Qs[d*128 + 64 + ty*4];
        float4 b0 = *(const float4*)&Ks[d*128 + tx*4];
        float4 b1 = *(const float4*)&Ks[d*128 + 64 + tx*4];
        float ar[8] = {a0.x,a0.y,a0.z,a0.w,a1.x,a1.y,a1.z,a1.w};
        float br[8] = {b0.x,b0.y,b0.z,b0.w,b1.x,b1.y,b1.z,b1.w};
        #pragma unroll
        for (int i = 0; i < 8; i++)
            #pragma unroll
            for (int j = 0; j < 8; j++) acc[i][j] += ar[i]*br[j];
    }

    float* Gb = &g_G[(size_t)b*LP*LP];
    #pragma unroll
    for (int i = 0; i < 8; i++){
        int p = p0 + ((i < 4) ? (ty*4 + i) : (64 + ty*4 + i - 4));
        if (p >= LP) continue;
        #pragma unroll
        for (int half = 0; half < 2; half++){
            int q = q0 + half*64 + tx*4;
            if (q + 4 <= LP){
                float4 v = make_float4(acc[i][half*4], acc[i][half*4+1],
                                       acc[i][half*4+2], acc[i][half*4+3]);
                *(float4*)&Gb[(size_t)p*LP + q] = v;
            } else {
                for (int j = 0; j < 4; j++)
                    if (q + j < LP) Gb[(size_t)p*LP + q + j] = acc[i][half*4 + j];
            }
        }
    }

    if (pt != qt){
        __syncthreads();
        #pragma unroll
        for (int i = 0; i < 8; i++){
            int pl = (i < 4) ? (ty*4 + i) : (64 + ty*4 + i - 4);
            #pragma unroll
            for (int j = 0; j < 8; j++){
                int ql = (j < 4) ? (tx*4 + j) : (64 + tx*4 + j - 4);
                stage[pl*133 + ql] = acc[i][j];
            }
        }
        __syncthreads();
        int wid = t >> 5, lane = t & 31;
        for (int r = wid; r < 128; r += 8){
            int q = q0 + r;
            if (q < LP){
                float4 o;
                o.x = stage[(lane*4 + 0)*133 + r];
                o.y = stage[(lane*4 + 1)*133 + r];
                o.z = stage[(lane*4 + 2)*133 + r];
                o.w = stage[(lane*4 + 3)*133 + r];
                *(float4*)&Gb[(size_t)q*LP + p0 + lane*4] = o;
            }
        }
    }
}

// ---------------- K4: reciprocal patch norms from diag(G) ----------------
__global__ void rn_kernel(){
    int b = blockIdx.y, li = blockIdx.x, lj = threadIdx.x;   // 64 threads
    const float* Gb = &g_G[(size_t)b*LP*LP];
    float s = 0.f;
    #pragma unroll
    for (int kh = 0; kh < 3; kh++)
        #pragma unroll
        for (int kw = 0; kw < 3; kw++){
            int p = (li + kh)*PW + lj + kw;
            s += Gb[(size_t)p*LP + p];
        }
    g_rn[b*LL + li*64 + lj] = 1.0f / fmaxf(sqrtf(s), 1e-12f);
}

// ---------------- K5a: split-K top-5 (each block scans 16 key tiles) ----------------
__global__ __launch_bounds__(256, 3) void stopk_part(){
    extern __shared__ float sm[];
    float* Bs  = sm;                 // [3][66][68] = 13464 floats
    float* rnq = sm + 13464;         // [64]
    float* rnk = rnq + 64;           // [64]
    float* Sc  = sm;                 // alias

    int b  = blockIdx.x >> 6;
    int li = blockIdx.x & 63;
    int sp = blockIdx.y;             // 0..3
    int t  = threadIdx.x, ty = t >> 4, tx = t & 15;
    int tr = t >> 5, tc2 = t & 31;
    int qq = t & 63, seg = t >> 6;

    if (t < 64) rnq[t] = g_rn[b*LL + li*64 + t];

    float tv[5]; int tix[5];
    #pragma unroll
    for (int i = 0; i < 5; i++){ tv[i] = -1e30f; tix[i] = 0; }

    const float* growbase = &g_G[(size_t)b*LP*LP] + (size_t)(li*PW)*LP;

    for (int mi = sp*16; mi < sp*16 + 16; mi++){
        __syncthreads();
        if (t < 64) rnk[t] = g_rn[b*LL + mi*64 + t];
        #pragma unroll
        for (int pass = 0; pass < 25; pass++){
            int row = pass*8 + tr;
            if (row < 198){
                int kh = (row >= 132) ? 2 : ((row >= 66) ? 1 : 0);
                const float2 v = *(const float2*)(growbase + (size_t)row*LP + (mi + kh)*PW + tc2*2);
                *(float2*)&Bs[row*68 + tc2*2] = v;
            }
        }
        if (t < 198){
            int row = t;
            int kh = (row >= 132) ? 2 : ((row >= 66) ? 1 : 0);
            const float2 v = *(const float2*)(growbase + (size_t)row*LP + (mi + kh)*PW + 64);
            *(float2*)&Bs[row*68 + 64] = v;
        }
        __syncthreads();

        int lj0 = ty*4, mj0 = tx*4;
        float S[4][4];
        #pragma unroll
        for (int i = 0; i < 4; i++)
            #pragma unroll
            for (int j = 0; j < 4; j++) S[i][j] = 0.f;

        #pragma unroll
        for (int kh = 0; kh < 3; kh++){
            float wv[6][6];
            #pragma unroll
            for (int r = 0; r < 6; r++){
                float4 u = *(const float4*)&Bs[(kh*66 + lj0 + r)*68 + mj0];
                float2 v = *(const float2*)&Bs[(kh*66 + lj0 + r)*68 + mj0 + 4];
                wv[r][0]=u.x; wv[r][1]=u.y; wv[r][2]=u.z; wv[r][3]=u.w; wv[r][4]=v.x; wv[r][5]=v.y;
            }
            #pragma unroll
            for (int kw = 0; kw < 3; kw++)
                #pragma unroll
                for (int i = 0; i < 4; i++)
                    #pragma unroll
                    for (int j = 0; j < 4; j++)
                        S[i][j] += wv[i+kw][j+kw];
        }
        __syncthreads();

        #pragma unroll
        for (int i = 0; i < 4; i++){
            float rq = rnq[lj0 + i];
            #pragma unroll
            for (int j = 0; j < 4; j++)
                Sc[(lj0 + i)*65 + mj0 + j] = S[i][j] * rq * rnk[mj0 + j];
        }
        __syncthreads();

        {   // all 256 threads: query qq, keys [seg*16, seg*16+16)
            const float* rowp = &Sc[qq*65 + seg*16];
            int k0 = (mi << 6) + seg*16;
            for (int jj = 0; jj < 16; jj++){
                float s = rowp[jj];
                if (s > tv[4]){
                    float v0 = s; int i0 = k0 + jj;
                    #pragma unroll
                    for (int p = 0; p < 5; p++){
                        if (v0 > tv[p]){
                            float tpv = tv[p]; int tpi = tix[p];
                            tv[p] = v0; tix[p] = i0;
                            v0 = tpv; i0 = tpi;
                        }
                    }
                }
            }
        }
    }

    // merge 4 segment lists per query (exact value-desc, index-asc), store top-5
    __syncthreads();
    float* mv = sm;                   // [64][20]
    int*   mx = (int*)(sm + 1280);    // [64][20]
    #pragma unroll
    for (int r = 0; r < 5; r++){
        mv[qq*20 + seg*5 + r] = tv[r];
        mx[qq*20 + seg*5 + r] = tix[r];
    }
    __syncthreads();
    if (t < 64){
        unsigned used = 0;
        int l = li*64 + t;
        for (int r = 0; r < 5; r++){
            float bvv = -3e38f; int bii = 0x7fffffff; int bc = 0;
            #pragma unroll
            for (int c = 0; c < 20; c++){
                if (used & (1u << c)) continue;
                float v = mv[t*20 + c]; int ii = mx[t*20 + c];
                if (v > bvv || (v == bvv && ii < bii)){ bvv = v; bii = ii; bc = c; }
            }
            used |= 1u << bc;
            g_pmv[((b*4 + sp)*5 + r)*LL + l] = bvv;
            g_pmi[((b*4 + sp)*5 + r)*LL + l] = bii;
        }
    }
}

// ---------------- K5b: merge 4 split lists into final ranks 1..4 ----------------
__global__ void topk_merge(){
    int b = blockIdx.y, li = blockIdx.x, q = threadIdx.x;  // 64 threads
    int l = li*64 + q;
    float mv[20]; int mx[20];
    #pragma unroll
    for (int sp = 0; sp < 4; sp++)
        #pragma unroll
        for (int r = 0; r < 5; r++){
            mv[sp*5 + r] = g_pmv[((b*4 + sp)*5 + r)*LL + l];
            mx[sp*5 + r] = g_pmi[((b*4 + sp)*5 + r)*LL + l];
        }
    unsigned used = 0;
    for (int r = 0; r < 5; r++){
        float bvv = -3e38f; int bii = 0x7fffffff; int bc = 0;
        #pragma unroll
        for (int c = 0; c < 20; c++){
            if (used & (1u << c)) continue;
            if (mv[c] > bvv || (mv[c] == bvv && mx[c] < bii)){ bvv = mv[c]; bii = mx[c]; bc = c; }
        }
        used |= 1u << bc;
        if (r >= 1){
            g_topv[(b*4 + (r-1))*LL + l] = bvv;
            g_topi[(b*4 + (r-1))*LL + l] = bii;
        }
    }
}

// ---------------- K6: gather+fold texture, 1x1 convs, pixel-split x2 ----------------
__global__ __launch_bounds__(256, 3) void final_kernel(const float* __restrict__ x,
                             const float* __restrict__ wt1, const float* __restrict__ bt1,
                             const float* __restrict__ wt2, const float* __restrict__ bt2,
                             float* __restrict__ out){
    extern __shared__ float sm[];
    float* Tc   = sm;                    // [256][32] (later aliased as fx[128][32])
    float* tex  = sm + 8192;             // [64][32]
    float* wbuf = sm + 10240;            // [64][64]
    float* msc  = sm + 14336;            // [4][32]
    int*   midx = (int*)(sm + 14464);    // [4][3][34]
    int b = blockIdx.x >> 6, i = blockIdx.x & 63;
    int h = blockIdx.y;                  // pixel half
    int t = threadIdx.x;
    int j0 = (t & 15)*2, c0 = (t >> 4)*4;

    for (int e = t; e < 4*3*34; e += 256){
        int br = e / 102, rr = (e / 34) % 3, jo = e % 34;
        int li = i - 1 + rr, lj = h*32 - 1 + jo;
        int v = 0;
        if ((unsigned)li < 64u && (unsigned)lj < 64u)
            v = g_topi[(b*4 + br)*LL + li*64 + lj];
        midx[e] = v;
    }
    if (t < 128){
        int br = t >> 5, j = t & 31;
        msc[t] = g_topv[(b*4 + br)*LL + i*64 + h*32 + j];
    }
    __syncthreads();

    const float* xp = &g_xpadR[(size_t)b*CC*LP];
    for (int e = t; e < 256*32; e += 256){
        int ci = e >> 5, j = e & 31;
        int br = ci >> 6, c = ci & 63;
        int jj = h*32 + j;
        const float* xpc = xp + c*LP;
        float sum = 0.f;
        #pragma unroll
        for (int kh = 0; kh < 3; kh++){
            int li = i + 1 - kh;
            if ((unsigned)li >= 64u) continue;
            int slot = 2 - kh;
            #pragma unroll
            for (int kw = 0; kw < 3; kw++){
                int lj = jj + 1 - kw;
                if ((unsigned)lj >= 64u) continue;
                int jo = lj - h*32 + 1;
                int m  = midx[br*102 + slot*34 + jo];
                int mi = m >> 6, mj = m & 63;
                sum += xpc[(mi + kh)*PW + mj + kw];
            }
        }
        Tc[e] = sum * msc[br*32 + j] * (1.0f/9.0f);
    }

    // texture = wt1 @ Tcat + bt1  (K=256, staged weight chunks of 64)
    float a[4][2];
    #pragma unroll
    for (int ii = 0; ii < 4; ii++){ a[ii][0] = 0.f; a[ii][1] = 0.f; }
    for (int cc = 0; cc < 4; cc++){
        __syncthreads();
        for (int e = t; e < 4096; e += 256)
            wbuf[e] = wt1[(e >> 6)*256 + cc*64 + (e & 63)];
        __syncthreads();
        #pragma unroll 4
        for (int cil = 0; cil < 64; cil++){
            float2 v = *(const float2*)&Tc[(cc*64 + cil)*32 + j0];
            #pragma unroll
            for (int ii = 0; ii < 4; ii++){
                float wv = wbuf[(c0 + ii)*64 + cil];
                a[ii][0] += wv*v.x; a[ii][1] += wv*v.y;
            }
        }
    }
    #pragma unroll
    for (int ii = 0; ii < 4; ii++){
        float bv = __ldg(&bt1[c0 + ii]);
        *(float2*)&tex[(c0 + ii)*32 + j0] = make_float2(a[ii][0]+bv, a[ii][1]+bv);
    }
    __syncthreads();

    // load feature & x half-rows into Tc region (Tc dead)
    float* fx = Tc;
    for (int e = t; e < 64*32; e += 256){
        int cch = e >> 5, j = e & 31;
        fx[e]           = g_feature[((b*CC + cch)*HH + i)*WW + h*32 + j];
        fx[64*32 + e]   = x[((b*CC + cch)*HH + i)*WW + h*32 + j];
    }

    // y = wt2 @ [feature; x; texture] + bt2  (K=192, 3 chunks)
    float a2[4][2];
    #pragma unroll
    for (int ii = 0; ii < 4; ii++){ a2[ii][0] = 0.f; a2[ii][1] = 0.f; }
    for (int cc = 0; cc < 3; cc++){
        __syncthreads();
        for (int e = t; e < 4096; e += 256)
            wbuf[e] = wt2[(e >> 6)*192 + cc*64 + (e & 63)];
        __syncthreads();
        const float* src = (cc == 2) ? tex : fx + cc*2048;
        #pragma unroll 4
        for (int cil = 0; cil < 64; cil++){
            float2 v = *(const float2*)&src[cil*32 + j0];
            #pragma unroll
            for (int ii = 0; ii < 4; ii++){
                float wv = wbuf[(c0 + ii)*64 + cil];
                a2[ii][0] += wv*v.x; a2[ii][1] += wv*v.y;
            }
        }
    }
    #pragma unroll
    for (int ii = 0; ii < 4; ii++){
        float bv = __ldg(&bt2[c0 + ii]);
        *(float2*)&out[((b*CC + c0 + ii)*HH + i)*WW + h*32 + j0] =
            make_float2(a2[ii][0]+bv, a2[ii][1]+bv);
    }
}

// ---------------- launch ----------------
extern "C" void kernel_launch(void* const* d_in, const int* in_sizes, int n_in,
                              void* d_out, int out_size){
    const float* x   = (const float*)d_in[0];
    const float* w1  = (const float*)d_in[1];
    const float* b1  = (const float*)d_in[2];
    const float* w2  = (const float*)d_in[3];
    const float* b2  = (const float*)d_in[4];
    const float* wt1 = (const float*)d_in[5];
    const float* bt1 = (const float*)d_in[6];
    const float* wt2 = (const float*)d_in[7];
    const float* bt2 = (const float*)d_in[8];
    float* out = (float*)d_out;

    const int CONV_SMEM = (13056 + 9216)*4;    // 89088
    const int GEMM_SMEM = 128*133*4;           // 68096
    const int STK_SMEM  = (13464 + 128)*4;     // 54368
    const int FIN_SMEM  = (14464 + 408)*4;     // 59488

    // one-time resource setup (runs on the uncaptured correctness call first)
    static cudaStream_t sB = nullptr;
    static cudaEvent_t evFork = nullptr, evJoin = nullptr;
    if (sB == nullptr){
        cudaStreamCreateWithFlags(&sB, cudaStreamNonBlocking);
        cudaEventCreateWithFlags(&evFork, cudaEventDisableTiming);
        cudaEventCreateWithFlags(&evJoin, cudaEventDisableTiming);
        cudaFuncSetAttribute(convg_kernel, cudaFuncAttributeMaxDynamicSharedMemorySize, CONV_SMEM);
        cudaFuncSetAttribute(gram_gemm,    cudaFuncAttributeMaxDynamicSharedMemorySize, GEMM_SMEM);
        cudaFuncSetAttribute(stopk_part,   cudaFuncAttributeMaxDynamicSharedMemorySize, STK_SMEM);
        cudaFuncSetAttribute(final_kernel, cudaFuncAttributeMaxDynamicSharedMemorySize, FIN_SMEM);
    }

    // main stream: pad, then fork conv branch onto sB
    pad_kernel<<<dim3(66, 4), 256>>>(x);
    cudaEventRecord(evFork, 0);
    cudaStreamWaitEvent(sB, evFork, 0);

    // branch B (independent of similarity pipeline): conv1 -> conv2
    convg_kernel<<<dim3(64, 4), 256, CONV_SMEM, sB>>>(w1, b1, 0);
    convg_kernel<<<dim3(64, 4), 256, CONV_SMEM, sB>>>(w2, b2, 1);
    cudaEventRecord(evJoin, sB);

    // branch A (critical path): gram -> rn -> stopk -> merge
    gram_gemm<<<dim3(630, 4), 256, GEMM_SMEM>>>();
    rn_kernel<<<dim3(64, 4), 64>>>();
    stopk_part<<<dim3(256, 4), 256, STK_SMEM>>>();
    topk_merge<<<dim3(64, 4), 64>>>();

    // join and finish
    cudaStreamWaitEvent(0, evJoin, 0);
    final_kernel<<<dim3(256, 2), 256, FIN_SMEM>>>(x, wt1, bt1, wt2, bt2, out);
}